// round 5
// baseline (speedup 1.0000x reference)
#include <cuda_runtime.h>
#include <math.h>

// Problem constants
#define E_ 2048
#define H_ 3
#define B_ 4
#define N_ 2048
#define MT (B_*N_)          // 8192 rows for x / mean / out

constexpr int BM = 128, BN = 128, BK = 16;

// Scratch (device globals: allocation-free rule)
__device__ float g_Q[(size_t)H_*B_*N_*E_];   // 192 MB  [h][b][n][e]
__device__ float g_K[(size_t)H_*B_*N_*E_];   // 192 MB
__device__ float g_V[(size_t)H_*B_*N_*E_];   // 192 MB
__device__ float g_P[(size_t)H_*B_*N_*N_];   // 192 MB  unnormalized exp(scores) [hb][n][m]
__device__ float g_Z[H_*B_*N_];              // column sums -> reciprocals
__device__ float g_mean[(size_t)B_*N_*E_];   // 64 MB

// ---------------------------------------------------------------------------
// Core 128x128 tile GEMM accumulator.
//   BT=true : C = A * B^T   (A:[M,K] row-major, B:[Ncols,K] row-major)
//   BT=false: C = A * B     (B:[K,Ncols] row-major), optional per-k row scale
// 256 threads; each owns an 8x8 register tile; accumulates into acc (no reset).
// ---------------------------------------------------------------------------
template<bool BT, bool SCALEB>
__device__ __forceinline__ void gemm_tile(
    const float* __restrict__ A, int lda,
    const float* __restrict__ Bm, int ldb,
    const float* __restrict__ invZ,   // only used when SCALEB
    int K,
    float (&acc)[8][8],
    float (*As)[BM], float (*Bs)[BN])
{
    const int tid = threadIdx.x;
    for (int kt = 0; kt < K; kt += BK) {
        // --- load A tile [BM x BK], store transposed As[k][row] ---
        #pragma unroll
        for (int u = 0; u < 2; u++) {
            int idx = tid * 2 + u;          // 0..511
            int row = idx >> 2;             // 0..127
            int k4  = idx & 3;              // 0..3 (float4 within the 16-k extent)
            float4 a = *reinterpret_cast<const float4*>(A + (size_t)row * lda + kt + k4 * 4);
            As[k4*4+0][row] = a.x;
            As[k4*4+1][row] = a.y;
            As[k4*4+2][row] = a.z;
            As[k4*4+3][row] = a.w;
        }
        // --- load B tile ---
        if (BT) {
            #pragma unroll
            for (int u = 0; u < 2; u++) {
                int idx = tid * 2 + u;
                int row = idx >> 2;         // output-column index 0..127
                int k4  = idx & 3;
                float4 b = *reinterpret_cast<const float4*>(Bm + (size_t)row * ldb + kt + k4 * 4);
                Bs[k4*4+0][row] = b.x;
                Bs[k4*4+1][row] = b.y;
                Bs[k4*4+2][row] = b.z;
                Bs[k4*4+3][row] = b.w;
            }
        } else {
            #pragma unroll
            for (int u = 0; u < 2; u++) {
                int idx  = tid * 2 + u;
                int krow = idx >> 5;        // 0..15
                int c4   = idx & 31;        // 0..31 float4 across 128 cols
                float4 b = *reinterpret_cast<const float4*>(Bm + (size_t)(kt + krow) * ldb + c4 * 4);
                float zs = 1.0f;
                if (SCALEB) zs = __ldg(invZ + kt + krow);
                Bs[krow][c4*4+0] = b.x * zs;
                Bs[krow][c4*4+1] = b.y * zs;
                Bs[krow][c4*4+2] = b.z * zs;
                Bs[krow][c4*4+3] = b.w * zs;
            }
        }
        __syncthreads();
        // --- compute ---
        const int tr = tid >> 4, tc = tid & 15;
        #pragma unroll
        for (int k = 0; k < BK; k++) {
            float ra[8], rb[8];
            *reinterpret_cast<float4*>(&ra[0]) = *reinterpret_cast<const float4*>(&As[k][tr*8]);
            *reinterpret_cast<float4*>(&ra[4]) = *reinterpret_cast<const float4*>(&As[k][tr*8+4]);
            *reinterpret_cast<float4*>(&rb[0]) = *reinterpret_cast<const float4*>(&Bs[k][tc*8]);
            *reinterpret_cast<float4*>(&rb[4]) = *reinterpret_cast<const float4*>(&Bs[k][tc*8+4]);
            #pragma unroll
            for (int i = 0; i < 8; i++)
                #pragma unroll
                for (int j = 0; j < 8; j++)
                    acc[i][j] += ra[i] * rb[j];
        }
        __syncthreads();
    }
}

// ---------------------------------------------------------------------------
// Stage 1: Q/K/V projections. z = t*3 + h, t in {Q,K,V}. C = x @ W[h]^T
// ---------------------------------------------------------------------------
__global__ void __launch_bounds__(256)
k_proj(const float* __restrict__ x, const float* __restrict__ Wq,
       const float* __restrict__ Wk, const float* __restrict__ Wv)
{
    __shared__ float As[BK][BM], Bs[BK][BN];
    int z = blockIdx.z;
    int t = z / H_, h = z - t * H_;
    const float* W = (t == 0 ? Wq : (t == 1 ? Wk : Wv)) + (size_t)h * E_ * E_;
    float*       C = (t == 0 ? g_Q : (t == 1 ? g_K : g_V)) + (size_t)h * MT * E_;
    const float* A  = x + (size_t)blockIdx.y * BM * E_;
    const float* Bp = W + (size_t)blockIdx.x * BN * E_;
    float acc[8][8] = {};
    gemm_tile<true, false>(A, E_, Bp, E_, nullptr, E_, acc, As, Bs);

    const int tr = threadIdx.x >> 4, tc = threadIdx.x & 15;
    size_t r0 = (size_t)blockIdx.y * BM + tr * 8;
    int    c0 = blockIdx.x * BN + tc * 8;
    #pragma unroll
    for (int i = 0; i < 8; i++) {
        *reinterpret_cast<float4*>(&C[(r0+i)*E_ + c0    ]) = *reinterpret_cast<float4*>(&acc[i][0]);
        *reinterpret_cast<float4*>(&C[(r0+i)*E_ + c0 + 4]) = *reinterpret_cast<float4*>(&acc[i][4]);
    }
}

// ---------------------------------------------------------------------------
// Stage 2: scores + fused exp2 epilogue + column-sum (over queries n) atomics.
// z = h*B_ + b. P[n,m] = exp2( (log2e/sqrt(E)) * Q_row_n . K_row_m )
// g_Z[z][m] += sum over this block's 128 n-rows.
// ---------------------------------------------------------------------------
__global__ void __launch_bounds__(256)
k_scores()
{
    __shared__ float As[BK][BM], Bs[BK][BN];
    int z = blockIdx.z;
    size_t base = (size_t)z * N_ * E_;
    const float* A  = g_Q + base + (size_t)blockIdx.y * BM * E_;
    const float* Bp = g_K + base + (size_t)blockIdx.x * BN * E_;
    float acc[8][8] = {};
    gemm_tile<true, false>(A, E_, Bp, E_, nullptr, E_, acc, As, Bs);

    const float s2 = 1.4426950408889634f / sqrtf((float)E_);  // log2(e)/sqrt(E)
    const int tr = threadIdx.x >> 4, tc = threadIdx.x & 15;
    float csum[8];
    #pragma unroll
    for (int j = 0; j < 8; j++) csum[j] = 0.0f;
    #pragma unroll
    for (int i = 0; i < 8; i++)
        #pragma unroll
        for (int j = 0; j < 8; j++) {
            float p = exp2f(acc[i][j] * s2);
            acc[i][j] = p;
            csum[j] += p;
        }

    float* P = g_P + (size_t)z * N_ * N_;
    size_t r0 = (size_t)blockIdx.y * BM + tr * 8;
    int    c0 = blockIdx.x * BN + tc * 8;
    #pragma unroll
    for (int i = 0; i < 8; i++) {
        *reinterpret_cast<float4*>(&P[(r0+i)*N_ + c0    ]) = *reinterpret_cast<float4*>(&acc[i][0]);
        *reinterpret_cast<float4*>(&P[(r0+i)*N_ + c0 + 4]) = *reinterpret_cast<float4*>(&acc[i][4]);
    }

    // reduce column sums across the 16 thread-rows via smem, then one atomic/col
    __syncthreads();
    float* red = &As[0][0];                   // 16*128 floats, exactly As
    #pragma unroll
    for (int j = 0; j < 8; j++) red[tr * 128 + tc * 8 + j] = csum[j];
    __syncthreads();
    if (threadIdx.x < 128) {
        float s = 0.0f;
        #pragma unroll
        for (int r = 0; r < 16; r++) s += red[r * 128 + threadIdx.x];
        atomicAdd(&g_Z[(size_t)z * N_ + blockIdx.x * BN + threadIdx.x], s);
    }
}

// ---------------------------------------------------------------------------
// Stage 3: attn + head-mean. z = b. Loops h internally; B-load scales V rows by
// 1/Z (g_Z holds reciprocals by now). mean[b,n,e] = (1/3) sum_h P_h @ (V_h/Z_h)
// ---------------------------------------------------------------------------
__global__ void __launch_bounds__(256)
k_attn()
{
    __shared__ float As[BK][BM], Bs[BK][BN];
    int b = blockIdx.z;
    float acc[8][8] = {};
    for (int h = 0; h < H_; h++) {
        size_t hb = (size_t)(h * B_ + b);
        const float* A  = g_P + hb * N_ * N_ + (size_t)blockIdx.y * BM * N_;
        const float* Bp = g_V + hb * N_ * E_ + blockIdx.x * BN;
        const float* iz = g_Z + hb * N_;
        gemm_tile<false, true>(A, N_, Bp, E_, iz, N_, acc, As, Bs);
    }
    const float inv_h = 1.0f / (float)H_;
    const int tr = threadIdx.x >> 4, tc = threadIdx.x & 15;
    float* C = g_mean + (size_t)b * N_ * E_;
    size_t r0 = (size_t)blockIdx.y * BM + tr * 8;
    int    c0 = blockIdx.x * BN + tc * 8;
    #pragma unroll
    for (int i = 0; i < 8; i++) {
        float4 v0 = make_float4(acc[i][0]*inv_h, acc[i][1]*inv_h, acc[i][2]*inv_h, acc[i][3]*inv_h);
        float4 v1 = make_float4(acc[i][4]*inv_h, acc[i][5]*inv_h, acc[i][6]*inv_h, acc[i][7]*inv_h);
        *reinterpret_cast<float4*>(&C[(r0+i)*E_ + c0    ]) = v0;
        *reinterpret_cast<float4*>(&C[(r0+i)*E_ + c0 + 4]) = v1;
    }
}

// ---------------------------------------------------------------------------
// Stage 4: out = mean @ fc_w^T + fc_b
// ---------------------------------------------------------------------------
__global__ void __launch_bounds__(256)
k_fc(const float* __restrict__ fc_w, const float* __restrict__ fc_b,
     float* __restrict__ out)
{
    __shared__ float As[BK][BM], Bs[BK][BN];
    const float* A  = g_mean + (size_t)blockIdx.y * BM * E_;
    const float* Bp = fc_w + (size_t)blockIdx.x * BN * E_;
    float acc[8][8] = {};
    gemm_tile<true, false>(A, E_, Bp, E_, nullptr, E_, acc, As, Bs);

    const int tr = threadIdx.x >> 4, tc = threadIdx.x & 15;
    size_t r0 = (size_t)blockIdx.y * BM + tr * 8;
    int    c0 = blockIdx.x * BN + tc * 8;
    float4 bia0 = *reinterpret_cast<const float4*>(&fc_b[c0]);
    float4 bia1 = *reinterpret_cast<const float4*>(&fc_b[c0 + 4]);
    #pragma unroll
    for (int i = 0; i < 8; i++) {
        float4 v0 = make_float4(acc[i][0]+bia0.x, acc[i][1]+bia0.y, acc[i][2]+bia0.z, acc[i][3]+bia0.w);
        float4 v1 = make_float4(acc[i][4]+bia1.x, acc[i][5]+bia1.y, acc[i][6]+bia1.z, acc[i][7]+bia1.w);
        *reinterpret_cast<float4*>(&out[(r0+i)*E_ + c0    ]) = v0;
        *reinterpret_cast<float4*>(&out[(r0+i)*E_ + c0 + 4]) = v1;
    }
}

// ---------------------------------------------------------------------------
// Small helpers: zero Z before scores; reciprocal after.
// ---------------------------------------------------------------------------
__global__ void k_zeroZ()
{
    int i = blockIdx.x * blockDim.x + threadIdx.x;
    if (i < H_ * B_ * N_) g_Z[i] = 0.0f;
}
__global__ void k_recipZ()
{
    int i = blockIdx.x * blockDim.x + threadIdx.x;
    if (i < H_ * B_ * N_) g_Z[i] = 1.0f / g_Z[i];
}

// ---------------------------------------------------------------------------
extern "C" void kernel_launch(void* const* d_in, const int* in_sizes, int n_in,
                              void* d_out, int out_size)
{
    const float* x    = (const float*)d_in[0];
    const float* Wq   = (const float*)d_in[1];
    const float* Wk   = (const float*)d_in[2];
    const float* Wv   = (const float*)d_in[3];
    const float* fc_w = (const float*)d_in[4];
    const float* fc_b = (const float*)d_in[5];
    float* out = (float*)d_out;

    k_zeroZ<<<(H_*B_*N_ + 255)/256, 256>>>();
    k_proj  <<<dim3(E_/BN, MT/BM, 3*H_), 256>>>(x, Wq, Wk, Wv);
    k_scores<<<dim3(N_/BN, N_/BM, H_*B_), 256>>>();
    k_recipZ<<<(H_*B_*N_ + 255)/256, 256>>>();
    k_attn  <<<dim3(E_/BN, N_/BM, B_), 256>>>();
    k_fc    <<<dim3(E_/BN, MT/BM), 256>>>(fc_w, fc_b, out);
}

// round 9
// speedup vs baseline: 4.4383x; 4.4383x over previous
#include <cuda_runtime.h>
#include <cstdint>
#include <math.h>

// Problem constants
#define E_ 2048
#define H_ 3
#define B_ 4
#define N_ 2048
#define MT (B_*N_)          // 8192 tokens

// GEMM tile: M=128, N=256, K=32 per iter; 512 threads (16 warps, 4x4)
constexpr int TM = 128, TN = 256, TK = 32;
constexpr int A_BYTES   = TM * TK * 4;        // 16 KB
constexpr int B_BYTES   = TN * TK * 4;        // 32 KB
constexpr int BUF_BYTES = A_BYTES + B_BYTES;  // 48 KB
constexpr int SMEM_GEMM = 2 * BUF_BYTES;      // 96 KB
constexpr int SMEM_PROJ = 16 * 2112 * 4;      // 135168 B (transpose staging > 96KB)

// Scratch (device globals: allocation-free rule)
__device__ float g_x  [(size_t)MT*E_];        // tf32-rounded x
__device__ float g_Wq [(size_t)H_*E_*E_];     // tf32-rounded weights
__device__ float g_Wk [(size_t)H_*E_*E_];
__device__ float g_Wv [(size_t)H_*E_*E_];
__device__ float g_fcw[(size_t)E_*E_];
__device__ float g_Q[(size_t)H_*B_*N_*E_];    // [h][t][e] (rounded)
__device__ float g_K[(size_t)H_*B_*N_*E_];    // [h][t][e] (rounded)
__device__ float g_V[(size_t)H_*B_*N_*E_];    // TRANSPOSED [hb][e][m]
__device__ float g_P[(size_t)H_*B_*N_*N_];    // [hb][n][m] = exp(scores) (rounded)
__device__ float g_Z[H_*B_*N_];               // col sums -> reciprocals
__device__ float g_mean[(size_t)B_*N_*E_];    // [t][e] (rounded)

// ---------------------------------------------------------------------------
// PTX helpers (plain sm_80+ features only — no 'a'-target instructions)
// ---------------------------------------------------------------------------
__device__ __forceinline__ uint32_t smem_u32(const void* p) {
    uint32_t a;
    asm("{ .reg .u64 t; cvta.to.shared.u64 t, %1; cvt.u32.u64 %0, t; }"
        : "=r"(a) : "l"(p));
    return a;
}
__device__ __forceinline__ float rna(float x) {
    float y; asm("cvt.rna.tf32.f32 %0, %1;" : "=f"(y) : "f"(x)); return y;
}
__device__ __forceinline__ void cp16(uint32_t dst, const void* src) {
    asm volatile("cp.async.cg.shared.global [%0], [%1], 16;" :: "r"(dst), "l"(src));
}
#define CP_COMMIT() asm volatile("cp.async.commit_group;" ::: "memory")
template<int Nw> __device__ __forceinline__ void cp_wait() {
    asm volatile("cp.async.wait_group %0;" :: "n"(Nw) : "memory");
}
__device__ __forceinline__ void ldsm4(uint32_t (&r)[4], uint32_t addr) {
    asm volatile("ldmatrix.sync.aligned.m8n8.x4.shared.b16 {%0,%1,%2,%3}, [%4];"
        : "=r"(r[0]), "=r"(r[1]), "=r"(r[2]), "=r"(r[3]) : "r"(addr));
}
__device__ __forceinline__ void mma_tf32(float (&d)[4], const uint32_t (&a)[4],
                                         uint32_t b0, uint32_t b1) {
    asm volatile(
        "mma.sync.aligned.m16n8k8.row.col.f32.tf32.tf32.f32 "
        "{%0,%1,%2,%3}, {%4,%5,%6,%7}, {%8,%9}, {%0,%1,%2,%3};"
        : "+f"(d[0]), "+f"(d[1]), "+f"(d[2]), "+f"(d[3])
        : "r"(a[0]), "r"(a[1]), "r"(a[2]), "r"(a[3]), "r"(b0), "r"(b1));
}

// ---------------------------------------------------------------------------
// Prefetch one 128x32 A tile + 256x32 B tile into swizzled smem via cp.async.
// Row layout: 32 floats (128B) per row; 16B chunk c swizzled to c ^ (row&7).
// ---------------------------------------------------------------------------
__device__ __forceinline__ void prefetch_tiles(
    const float* __restrict__ Ag, const float* __restrict__ Bg,
    int lda, int ldb, int kt, uint32_t sA, uint32_t sB, int tid)
{
    #pragma unroll
    for (int i = 0; i < 2; i++) {
        int f = tid + i * 512, row = f >> 3, c4 = f & 7;
        cp16(sA + row * 128 + ((c4 ^ (row & 7)) << 4),
             Ag + (size_t)row * lda + kt + c4 * 4);
    }
    #pragma unroll
    for (int i = 0; i < 4; i++) {
        int f = tid + i * 512, row = f >> 3, c4 = f & 7;
        cp16(sB + row * 128 + ((c4 ^ (row & 7)) << 4),
             Bg + (size_t)row * ldb + kt + c4 * 4);
    }
}

// ---------------------------------------------------------------------------
// Compute 128x256 += A(128x32) * B(256x32)^T from swizzled smem tiles.
// Warp (mw,nw) owns 32x64. Fragments loaded via ldmatrix (b16 x4 trick).
// ---------------------------------------------------------------------------
__device__ __forceinline__ void compute_tiles(
    uint32_t sA, uint32_t sB, int mw, int nw, int lane, float (&acc)[2][8][4])
{
    const int g  = lane >> 3;       // ldmatrix address group 0..3
    const int i8 = lane & 7;
    const int rA0 = mw + ((g & 1) << 3) + i8;   // +16 per M-tile
    const int rB0 = nw + ((g >> 1) << 3) + i8;  // +16 per N-tile-pair
    const int chA = (g >> 1), chB = (g & 1);
    #pragma unroll
    for (int kc = 0; kc < 8; kc += 2) {         // 4 k-steps of 8
        uint32_t a[2][4];
        #pragma unroll
        for (int i = 0; i < 2; i++) {
            int row = rA0 + i * 16, ch = kc + chA;
            ldsm4(a[i], sA + row * 128 + ((ch ^ (row & 7)) << 4));
        }
        #pragma unroll
        for (int j2 = 0; j2 < 4; j2++) {
            uint32_t b[4];
            int row = rB0 + j2 * 16, ch = kc + chB;
            ldsm4(b, sB + row * 128 + ((ch ^ (row & 7)) << 4));
            #pragma unroll
            for (int i = 0; i < 2; i++) {
                mma_tf32(acc[i][2*j2],   a[i], b[0], b[1]);
                mma_tf32(acc[i][2*j2+1], a[i], b[2], b[3]);
            }
        }
    }
}

// ---------------------------------------------------------------------------
// Double-buffered mainloop; NSEG K-segments of 2048 each (attn uses 3 heads).
// ---------------------------------------------------------------------------
template<int NSEG>
__device__ __forceinline__ void mainloop(
    const float* A0, const float* A1, const float* A2,
    const float* B0, const float* B1, const float* B2,
    int lda, int ldb, uint32_t sbase, int tid, int mw, int nw, int lane,
    float (&acc)[2][8][4])
{
    const int total = NSEG * (E_ / TK);
    prefetch_tiles(A0, B0, lda, ldb, 0, sbase, sbase + A_BYTES, tid);
    CP_COMMIT();
    for (int c = 0; c < total; c++) {
        if (c + 1 < total) {
            int cn = c + 1, s = cn >> 6;
            const float* Ag = (s == 0) ? A0 : (s == 1 ? A1 : A2);
            const float* Bg = (s == 0) ? B0 : (s == 1 ? B1 : B2);
            uint32_t off = (uint32_t)(cn & 1) * BUF_BYTES;
            prefetch_tiles(Ag, Bg, lda, ldb, (cn & 63) * TK,
                           sbase + off, sbase + off + A_BYTES, tid);
            CP_COMMIT();
            cp_wait<1>();
        } else {
            cp_wait<0>();
        }
        __syncthreads();
        uint32_t off = (uint32_t)(c & 1) * BUF_BYTES;
        compute_tiles(sbase + off, sbase + off + A_BYTES, mw, nw, lane, acc);
        __syncthreads();
    }
}

// Common per-thread ids
struct Ids { int tid, lane, wid, mw, nw, qr, qc; };
__device__ __forceinline__ Ids make_ids() {
    Ids d;
    d.tid = threadIdx.x; d.lane = d.tid & 31; d.wid = d.tid >> 5;
    d.mw = (d.wid & 3) * 32; d.nw = (d.wid >> 2) * 64;
    d.qr = d.lane >> 2; d.qc = d.lane & 3;
    return d;
}

// ---------------------------------------------------------------------------
// Stage 0: RNA-round inputs into device scratch (x, Wq, Wk, Wv, fc_w).
// ---------------------------------------------------------------------------
__global__ void __launch_bounds__(256)
k_round(const float4* __restrict__ x,  const float4* __restrict__ Wq,
        const float4* __restrict__ Wk, const float4* __restrict__ Wv,
        const float4* __restrict__ fcw)
{
    const size_t nx = (size_t)MT * E_ / 4, nw = (size_t)H_ * E_ * E_ / 4,
                 nf = (size_t)E_ * E_ / 4;
    size_t i = (size_t)blockIdx.x * blockDim.x + threadIdx.x;
    const float4* src; float* dst; size_t off;
    if      (i < nx)            { src = x;   dst = g_x;   off = i; }
    else if (i < nx + nw)       { src = Wq;  dst = g_Wq;  off = i - nx; }
    else if (i < nx + 2*nw)     { src = Wk;  dst = g_Wk;  off = i - nx - nw; }
    else if (i < nx + 3*nw)     { src = Wv;  dst = g_Wv;  off = i - nx - 2*nw; }
    else if (i < nx + 3*nw + nf){ src = fcw; dst = g_fcw; off = i - nx - 3*nw; }
    else return;
    float4 v = src[off];
    v.x = rna(v.x); v.y = rna(v.y); v.z = rna(v.z); v.w = rna(v.w);
    reinterpret_cast<float4*>(dst)[off] = v;
}

// ---------------------------------------------------------------------------
// Stage 1: projections. z: t=z/3 (Q,K,V), h=z%3. C = x @ W[h]^T.
// Q,K row-major rounded; V stored TRANSPOSED [hb][e][m] via smem transpose.
// ---------------------------------------------------------------------------
__global__ void __launch_bounds__(512, 1)
k_proj()
{
    extern __shared__ char dsm[];
    Ids d = make_ids();
    int z = blockIdx.z, t = z / H_, h = z - t * H_;
    const float* W = (t == 0 ? g_Wq : (t == 1 ? g_Wk : g_Wv)) + (size_t)h * E_ * E_;
    const float* A  = g_x + (size_t)blockIdx.y * TM * E_;
    const float* Bm = W + (size_t)blockIdx.x * TN * E_;
    float acc[2][8][4] = {};
    mainloop<1>(A, A, A, Bm, Bm, Bm, E_, E_, smem_u32(dsm),
                d.tid, d.mw, d.nw, d.lane, acc);

    if (t < 2) {
        float* C = (t == 0 ? g_Q : g_K) + (size_t)h * MT * E_;
        #pragma unroll
        for (int i = 0; i < 2; i++) {
            size_t r = (size_t)blockIdx.y * TM + d.mw + i * 16 + d.qr;
            #pragma unroll
            for (int j = 0; j < 8; j++) {
                int cn = blockIdx.x * TN + d.nw + j * 8 + d.qc * 2;
                *reinterpret_cast<float2*>(&C[r * E_ + cn]) =
                    make_float2(rna(acc[i][j][0]), rna(acc[i][j][1]));
                *reinterpret_cast<float2*>(&C[(r + 8) * E_ + cn]) =
                    make_float2(rna(acc[i][j][2]), rna(acc[i][j][3]));
            }
        }
    } else {
        // transpose 32x64 warp tile through smem, write coalesced Vt rows
        float* tw = reinterpret_cast<float*>(dsm) + d.wid * 2112;  // [64][33]
        #pragma unroll
        for (int i = 0; i < 2; i++) {
            int ml = i * 16 + d.qr;
            #pragma unroll
            for (int j = 0; j < 8; j++) {
                int el = j * 8 + d.qc * 2;
                tw[(el    ) * 33 + ml    ] = acc[i][j][0];
                tw[(el + 1) * 33 + ml    ] = acc[i][j][1];
                tw[(el    ) * 33 + ml + 8] = acc[i][j][2];
                tw[(el + 1) * 33 + ml + 8] = acc[i][j][3];
            }
        }
        __syncwarp();
        int b  = (blockIdx.y * TM) >> 11;
        int m0 = (blockIdx.y * TM + d.mw) & (N_ - 1);
        size_t basev = (size_t)(h * B_ + b) * E_ * N_;
        #pragma unroll
        for (int it = 0; it < 16; it++) {
            int el = it * 4 + (d.lane >> 3);
            int m4 = (d.lane & 7) * 4;
            float4 v = make_float4(tw[el*33 + m4], tw[el*33 + m4 + 1],
                                   tw[el*33 + m4 + 2], tw[el*33 + m4 + 3]);
            int e = blockIdx.x * TN + d.nw + el;
            *reinterpret_cast<float4*>(&g_V[basev + (size_t)e * N_ + m0 + m4]) = v;
        }
    }
}

// ---------------------------------------------------------------------------
// Stage 2: scores + exp2 + column sums (softmax over query axis n).
// ---------------------------------------------------------------------------
__global__ void __launch_bounds__(512, 1)
k_scores()
{
    extern __shared__ char dsm[];
    Ids d = make_ids();
    int z = blockIdx.z;
    const float* A  = g_Q + (size_t)z * N_ * E_ + (size_t)blockIdx.y * TM * E_;
    const float* Bm = g_K + (size_t)z * N_ * E_ + (size_t)blockIdx.x * TN * E_;
    float acc[2][8][4] = {};
    mainloop<1>(A, A, A, Bm, Bm, Bm, E_, E_, smem_u32(dsm),
                d.tid, d.mw, d.nw, d.lane, acc);

    const float s2 = 1.4426950408889634f / sqrtf((float)E_);
    float* P  = g_P + (size_t)z * N_ * N_;
    float* Zb = g_Z + (size_t)z * N_;
    float cs0[8], cs1[8];
    #pragma unroll
    for (int j = 0; j < 8; j++) { cs0[j] = 0.f; cs1[j] = 0.f; }
    #pragma unroll
    for (int i = 0; i < 2; i++) {
        size_t r = (size_t)blockIdx.y * TM + d.mw + i * 16 + d.qr;
        #pragma unroll
        for (int j = 0; j < 8; j++) {
            int cn = blockIdx.x * TN + d.nw + j * 8 + d.qc * 2;
            float p0 = rna(exp2f(acc[i][j][0] * s2));
            float p1 = rna(exp2f(acc[i][j][1] * s2));
            float p2 = rna(exp2f(acc[i][j][2] * s2));
            float p3 = rna(exp2f(acc[i][j][3] * s2));
            *reinterpret_cast<float2*>(&P[r * N_ + cn])       = make_float2(p0, p1);
            *reinterpret_cast<float2*>(&P[(r + 8) * N_ + cn]) = make_float2(p2, p3);
            cs0[j] += p0 + p2;
            cs1[j] += p1 + p3;
        }
    }
    #pragma unroll
    for (int j = 0; j < 8; j++) {
        float s0 = cs0[j], s1 = cs1[j];
        #pragma unroll
        for (int o = 4; o < 32; o <<= 1) {
            s0 += __shfl_xor_sync(0xFFFFFFFFu, s0, o);
            s1 += __shfl_xor_sync(0xFFFFFFFFu, s1, o);
        }
        if (d.lane < 4) {
            int cn = blockIdx.x * TN + d.nw + j * 8 + d.lane * 2;
            atomicAdd(&Zb[cn], s0);
            atomicAdd(&Zb[cn + 1], s1);
        }
    }
}

// ---------------------------------------------------------------------------
// Helpers: zero Z; Z -> 1/Z; Vt[hb][e][m] *= invZ[hb][m] (RNA-rounded).
// ---------------------------------------------------------------------------
__global__ void k_zeroZ() {
    int i = blockIdx.x * blockDim.x + threadIdx.x;
    if (i < H_ * B_ * N_) g_Z[i] = 0.0f;
}
__global__ void k_recipZ() {
    int i = blockIdx.x * blockDim.x + threadIdx.x;
    if (i < H_ * B_ * N_) g_Z[i] = 1.0f / g_Z[i];
}
__global__ void k_scaleV() {
    size_t i4 = (size_t)blockIdx.x * blockDim.x + threadIdx.x;
    if (i4 >= (size_t)H_ * B_ * E_ * N_ / 4) return;
    size_t m4 = i4 % (N_ / 4);
    size_t hb = i4 / ((size_t)E_ * N_ / 4);
    float4 v  = *reinterpret_cast<float4*>(g_V + i4 * 4);
    float4 zz = *reinterpret_cast<const float4*>(g_Z + hb * N_ + m4 * 4);
    v.x = rna(v.x * zz.x); v.y = rna(v.y * zz.y);
    v.z = rna(v.z * zz.z); v.w = rna(v.w * zz.w);
    *reinterpret_cast<float4*>(g_V + i4 * 4) = v;
}

// ---------------------------------------------------------------------------
// Stage 4: attn + head-mean. z = b; 3 K-segments (one per head) accumulate.
// ---------------------------------------------------------------------------
__global__ void __launch_bounds__(512, 1)
k_attn()
{
    extern __shared__ char dsm[];
    Ids d = make_ids();
    int b = blockIdx.z;
    const float *Aa[3], *Bb[3];
    #pragma unroll
    for (int h = 0; h < H_; h++) {
        size_t hb = (size_t)(h * B_ + b);
        Aa[h] = g_P + hb * N_ * N_ + (size_t)blockIdx.y * TM * N_;
        Bb[h] = g_V + hb * E_ * N_ + (size_t)blockIdx.x * TN * N_;
    }
    float acc[2][8][4] = {};
    mainloop<3>(Aa[0], Aa[1], Aa[2], Bb[0], Bb[1], Bb[2], N_, N_,
                smem_u32(dsm), d.tid, d.mw, d.nw, d.lane, acc);

    const float inv3 = 1.0f / (float)H_;
    float* C = g_mean + (size_t)b * N_ * E_;
    #pragma unroll
    for (int i = 0; i < 2; i++) {
        size_t r = (size_t)blockIdx.y * TM + d.mw + i * 16 + d.qr;
        #pragma unroll
        for (int j = 0; j < 8; j++) {
            int cn = blockIdx.x * TN + d.nw + j * 8 + d.qc * 2;
            *reinterpret_cast<float2*>(&C[r * E_ + cn]) =
                make_float2(rna(acc[i][j][0] * inv3), rna(acc[i][j][1] * inv3));
            *reinterpret_cast<float2*>(&C[(r + 8) * E_ + cn]) =
                make_float2(rna(acc[i][j][2] * inv3), rna(acc[i][j][3] * inv3));
        }
    }
}

// ---------------------------------------------------------------------------
// Stage 5: out = mean @ fc_w^T + fc_b (bias in full fp32).
// ---------------------------------------------------------------------------
__global__ void __launch_bounds__(512, 1)
k_fc(const float* __restrict__ fc_b, float* __restrict__ out)
{
    extern __shared__ char dsm[];
    Ids d = make_ids();
    const float* A  = g_mean + (size_t)blockIdx.y * TM * E_;
    const float* Bm = g_fcw + (size_t)blockIdx.x * TN * E_;
    float acc[2][8][4] = {};
    mainloop<1>(A, A, A, Bm, Bm, Bm, E_, E_, smem_u32(dsm),
                d.tid, d.mw, d.nw, d.lane, acc);

    #pragma unroll
    for (int i = 0; i < 2; i++) {
        size_t r = (size_t)blockIdx.y * TM + d.mw + i * 16 + d.qr;
        #pragma unroll
        for (int j = 0; j < 8; j++) {
            int cn = blockIdx.x * TN + d.nw + j * 8 + d.qc * 2;
            float2 bia = *reinterpret_cast<const float2*>(&fc_b[cn]);
            *reinterpret_cast<float2*>(&out[r * E_ + cn]) =
                make_float2(acc[i][j][0] + bia.x, acc[i][j][1] + bia.y);
            *reinterpret_cast<float2*>(&out[(r + 8) * E_ + cn]) =
                make_float2(acc[i][j][2] + bia.x, acc[i][j][3] + bia.y);
        }
    }
}

// ---------------------------------------------------------------------------
extern "C" void kernel_launch(void* const* d_in, const int* in_sizes, int n_in,
                              void* d_out, int out_size)
{
    const float* x    = (const float*)d_in[0];
    const float* Wq   = (const float*)d_in[1];
    const float* Wk   = (const float*)d_in[2];
    const float* Wv   = (const float*)d_in[3];
    const float* fc_w = (const float*)d_in[4];
    const float* fc_b = (const float*)d_in[5];
    float* out = (float*)d_out;

    // idempotent, cheap — no static guards (harness rule)
    cudaFuncSetAttribute(k_proj,   cudaFuncAttributeMaxDynamicSharedMemorySize, SMEM_PROJ);
    cudaFuncSetAttribute(k_scores, cudaFuncAttributeMaxDynamicSharedMemorySize, SMEM_GEMM);
    cudaFuncSetAttribute(k_attn,   cudaFuncAttributeMaxDynamicSharedMemorySize, SMEM_GEMM);
    cudaFuncSetAttribute(k_fc,     cudaFuncAttributeMaxDynamicSharedMemorySize, SMEM_GEMM);

    const size_t nround = (size_t)MT*E_/4 + 3*(size_t)H_*E_*E_/4 + (size_t)E_*E_/4;
    k_round <<<(int)((nround + 255) / 256), 256>>>(
        (const float4*)x, (const float4*)Wq, (const float4*)Wk,
        (const float4*)Wv, (const float4*)fc_w);
    k_zeroZ <<<(H_*B_*N_ + 255)/256, 256>>>();
    k_proj  <<<dim3(E_/TN, MT/TM, 3*H_), 512, SMEM_PROJ>>>();
    k_scores<<<dim3(N_/TN, N_/TM, H_*B_), 512, SMEM_GEMM>>>();
    k_recipZ<<<(H_*B_*N_ + 255)/256, 256>>>();
    k_scaleV<<<(int)(((size_t)H_*B_*E_*N_/4 + 255)/256), 256>>>();
    k_attn  <<<dim3(E_/TN, N_/TM, B_), 512, SMEM_GEMM>>>();
    k_fc    <<<dim3(E_/TN, MT/TM), 512, SMEM_GEMM>>>(fc_b, out);
}

// round 10
// speedup vs baseline: 5.0677x; 1.1418x over previous
#include <cuda_runtime.h>
#include <cstdint>
#include <math.h>

// Problem constants
#define E_ 2048
#define H_ 3
#define B_ 4
#define N_ 2048
#define MT (B_*N_)          // 8192 tokens

// GEMM tile: M=128, N=128, K=32 per iter; 256 threads (8 warps, 4x2),
// 3-stage cp.async pipeline, 2 CTAs/SM.
constexpr int TM = 128, TN = 128, TK = 32;
constexpr int STAGES = 3;
constexpr int A_BYTES   = TM * TK * 4;        // 16 KB
constexpr int B_BYTES   = TN * TK * 4;        // 16 KB
constexpr int BUF_BYTES = A_BYTES + B_BYTES;  // 32 KB
constexpr int SMEM_GEMM = STAGES * BUF_BYTES; // 96 KB

// Scratch (device globals: allocation-free rule)
__device__ float g_x  [(size_t)MT*E_];        // tf32-rounded x
__device__ float g_Wq [(size_t)H_*E_*E_];     // tf32-rounded weights
__device__ float g_Wk [(size_t)H_*E_*E_];
__device__ float g_Wv [(size_t)H_*E_*E_];
__device__ float g_fcw[(size_t)E_*E_];
__device__ float g_Q[(size_t)H_*B_*N_*E_];    // [h][t][e] (rounded)
__device__ float g_K[(size_t)H_*B_*N_*E_];    // [h][t][e] (rounded)
__device__ float g_V[(size_t)H_*B_*N_*E_];    // TRANSPOSED [hb][e][m]
__device__ float g_P[(size_t)H_*B_*N_*N_];    // [hb][n][m] = exp(scores) (rounded)
__device__ float g_Z[H_*B_*N_];               // col sums -> reciprocals
__device__ float g_mean[(size_t)B_*N_*E_];    // [t][e] (rounded)

// ---------------------------------------------------------------------------
// PTX helpers (plain sm_80+ features only — no 'a'-target instructions)
// ---------------------------------------------------------------------------
__device__ __forceinline__ uint32_t smem_u32(const void* p) {
    uint32_t a;
    asm("{ .reg .u64 t; cvta.to.shared.u64 t, %1; cvt.u32.u64 %0, t; }"
        : "=r"(a) : "l"(p));
    return a;
}
__device__ __forceinline__ float rna(float x) {
    float y; asm("cvt.rna.tf32.f32 %0, %1;" : "=f"(y) : "f"(x)); return y;
}
__device__ __forceinline__ void cp16(uint32_t dst, const void* src) {
    asm volatile("cp.async.cg.shared.global [%0], [%1], 16;" :: "r"(dst), "l"(src));
}
#define CP_COMMIT() asm volatile("cp.async.commit_group;" ::: "memory")
template<int Nw> __device__ __forceinline__ void cp_wait() {
    asm volatile("cp.async.wait_group %0;" :: "n"(Nw) : "memory");
}
__device__ __forceinline__ void ldsm4(uint32_t (&r)[4], uint32_t addr) {
    asm volatile("ldmatrix.sync.aligned.m8n8.x4.shared.b16 {%0,%1,%2,%3}, [%4];"
        : "=r"(r[0]), "=r"(r[1]), "=r"(r[2]), "=r"(r[3]) : "r"(addr));
}
__device__ __forceinline__ void mma_tf32(float (&d)[4], const uint32_t (&a)[4],
                                         uint32_t b0, uint32_t b1) {
    asm volatile(
        "mma.sync.aligned.m16n8k8.row.col.f32.tf32.tf32.f32 "
        "{%0,%1,%2,%3}, {%4,%5,%6,%7}, {%8,%9}, {%0,%1,%2,%3};"
        : "+f"(d[0]), "+f"(d[1]), "+f"(d[2]), "+f"(d[3])
        : "r"(a[0]), "r"(a[1]), "r"(a[2]), "r"(a[3]), "r"(b0), "r"(b1));
}

// ---------------------------------------------------------------------------
// Prefetch one 128x32 A tile + 128x32 B tile into swizzled smem via cp.async.
// Row layout: 32 floats (128B) per row; 16B chunk c swizzled to c ^ (row&7).
// ---------------------------------------------------------------------------
__device__ __forceinline__ void prefetch_tiles(
    const float* __restrict__ Ag, const float* __restrict__ Bg,
    int lda, int ldb, int kt, uint32_t sA, uint32_t sB, int tid)
{
    #pragma unroll
    for (int i = 0; i < 4; i++) {
        int f = tid + i * 256, row = f >> 3, c4 = f & 7;
        cp16(sA + row * 128 + ((c4 ^ (row & 7)) << 4),
             Ag + (size_t)row * lda + kt + c4 * 4);
    }
    #pragma unroll
    for (int i = 0; i < 4; i++) {
        int f = tid + i * 256, row = f >> 3, c4 = f & 7;
        cp16(sB + row * 128 + ((c4 ^ (row & 7)) << 4),
             Bg + (size_t)row * ldb + kt + c4 * 4);
    }
}

// ---------------------------------------------------------------------------
// Compute 128x128 += A(128x32) * B(128x32)^T from swizzled smem tiles.
// Warp (mw,nw) owns 32x64. Fragments loaded via ldmatrix (b16 x4 trick).
// ---------------------------------------------------------------------------
__device__ __forceinline__ void compute_tiles(
    uint32_t sA, uint32_t sB, int mw, int nw, int lane, float (&acc)[2][8][4])
{
    const int g  = lane >> 3;       // ldmatrix address group 0..3
    const int i8 = lane & 7;
    const int rA0 = mw + ((g & 1) << 3) + i8;   // +16 per M-tile
    const int rB0 = nw + ((g >> 1) << 3) + i8;  // +16 per N-tile-pair
    const int chA = (g >> 1), chB = (g & 1);
    #pragma unroll
    for (int kc = 0; kc < 8; kc += 2) {         // 4 k-steps of 8
        uint32_t a[2][4];
        #pragma unroll
        for (int i = 0; i < 2; i++) {
            int row = rA0 + i * 16, ch = kc + chA;
            ldsm4(a[i], sA + row * 128 + ((ch ^ (row & 7)) << 4));
        }
        #pragma unroll
        for (int j2 = 0; j2 < 4; j2++) {
            uint32_t b[4];
            int row = rB0 + j2 * 16, ch = kc + chB;
            ldsm4(b, sB + row * 128 + ((ch ^ (row & 7)) << 4));
            #pragma unroll
            for (int i = 0; i < 2; i++) {
                mma_tf32(acc[i][2*j2],   a[i], b[0], b[1]);
                mma_tf32(acc[i][2*j2+1], a[i], b[2], b[3]);
            }
        }
    }
}

// ---------------------------------------------------------------------------
// 3-stage cp.async mainloop; NSEG K-segments of 2048 (attn uses 3 heads).
// ---------------------------------------------------------------------------
template<int NSEG>
__device__ __forceinline__ void mainloop(
    const float* A0, const float* A1, const float* A2,
    const float* B0, const float* B1, const float* B2,
    int lda, int ldb, uint32_t sbase, int tid, int mw, int nw, int lane,
    float (&acc)[2][8][4])
{
    const int total = NSEG * (E_ / TK);
    prefetch_tiles(A0, B0, lda, ldb, 0, sbase, sbase + A_BYTES, tid);
    CP_COMMIT();
    prefetch_tiles(A0, B0, lda, ldb, TK, sbase + BUF_BYTES,
                   sbase + BUF_BYTES + A_BYTES, tid);
    CP_COMMIT();
    for (int c = 0; c < total; c++) {
        int cn = c + 2;
        if (cn < total) {
            int s = cn >> 6;
            const float* Ag = (s == 0) ? A0 : (s == 1 ? A1 : A2);
            const float* Bg = (s == 0) ? B0 : (s == 1 ? B1 : B2);
            uint32_t off = (uint32_t)(cn % STAGES) * BUF_BYTES;
            prefetch_tiles(Ag, Bg, lda, ldb, (cn & 63) * TK,
                           sbase + off, sbase + off + A_BYTES, tid);
            CP_COMMIT();
            cp_wait<2>();
        } else {
            cp_wait<0>();
        }
        __syncthreads();
        uint32_t off = (uint32_t)(c % STAGES) * BUF_BYTES;
        compute_tiles(sbase + off, sbase + off + A_BYTES, mw, nw, lane, acc);
        __syncthreads();
    }
}

// Common per-thread ids (8 warps: 4 along M, 2 along N)
struct Ids { int tid, lane, wid, mw, nw, qr, qc; };
__device__ __forceinline__ Ids make_ids() {
    Ids d;
    d.tid = threadIdx.x; d.lane = d.tid & 31; d.wid = d.tid >> 5;
    d.mw = (d.wid & 3) * 32; d.nw = (d.wid >> 2) * 64;
    d.qr = d.lane >> 2; d.qc = d.lane & 3;
    return d;
}

// ---------------------------------------------------------------------------
// Stage 0: RNA-round inputs into device scratch (x, Wq, Wk, Wv, fc_w).
// ---------------------------------------------------------------------------
__global__ void __launch_bounds__(256)
k_round(const float4* __restrict__ x,  const float4* __restrict__ Wq,
        const float4* __restrict__ Wk, const float4* __restrict__ Wv,
        const float4* __restrict__ fcw)
{
    const size_t nx = (size_t)MT * E_ / 4, nw = (size_t)H_ * E_ * E_ / 4,
                 nf = (size_t)E_ * E_ / 4;
    size_t i = (size_t)blockIdx.x * blockDim.x + threadIdx.x;
    const float4* src; float* dst; size_t off;
    if      (i < nx)            { src = x;   dst = g_x;   off = i; }
    else if (i < nx + nw)       { src = Wq;  dst = g_Wq;  off = i - nx; }
    else if (i < nx + 2*nw)     { src = Wk;  dst = g_Wk;  off = i - nx - nw; }
    else if (i < nx + 3*nw)     { src = Wv;  dst = g_Wv;  off = i - nx - 2*nw; }
    else if (i < nx + 3*nw + nf){ src = fcw; dst = g_fcw; off = i - nx - 3*nw; }
    else return;
    float4 v = src[off];
    v.x = rna(v.x); v.y = rna(v.y); v.z = rna(v.z); v.w = rna(v.w);
    reinterpret_cast<float4*>(dst)[off] = v;
}

// ---------------------------------------------------------------------------
// Stage 1: projections. z: t=z/3 (Q,K,V), h=z%3. C = x @ W[h]^T.
// Q,K row-major rounded; V stored TRANSPOSED [hb][e][m] via smem transpose.
// ---------------------------------------------------------------------------
__global__ void __launch_bounds__(256, 2)
k_proj()
{
    extern __shared__ char dsm[];
    Ids d = make_ids();
    int z = blockIdx.z, t = z / H_, h = z - t * H_;
    const float* W = (t == 0 ? g_Wq : (t == 1 ? g_Wk : g_Wv)) + (size_t)h * E_ * E_;
    const float* A  = g_x + (size_t)blockIdx.y * TM * E_;
    const float* Bm = W + (size_t)blockIdx.x * TN * E_;
    float acc[2][8][4] = {};
    mainloop<1>(A, A, A, Bm, Bm, Bm, E_, E_, smem_u32(dsm),
                d.tid, d.mw, d.nw, d.lane, acc);

    if (t < 2) {
        float* C = (t == 0 ? g_Q : g_K) + (size_t)h * MT * E_;
        #pragma unroll
        for (int i = 0; i < 2; i++) {
            size_t r = (size_t)blockIdx.y * TM + d.mw + i * 16 + d.qr;
            #pragma unroll
            for (int j = 0; j < 8; j++) {
                int cn = blockIdx.x * TN + d.nw + j * 8 + d.qc * 2;
                *reinterpret_cast<float2*>(&C[r * E_ + cn]) =
                    make_float2(rna(acc[i][j][0]), rna(acc[i][j][1]));
                *reinterpret_cast<float2*>(&C[(r + 8) * E_ + cn]) =
                    make_float2(rna(acc[i][j][2]), rna(acc[i][j][3]));
            }
        }
    } else {
        // transpose 32x64 warp tile through smem, write coalesced Vt rows
        float* tw = reinterpret_cast<float*>(dsm) + d.wid * 2112;  // [64][33]
        #pragma unroll
        for (int i = 0; i < 2; i++) {
            int ml = i * 16 + d.qr;
            #pragma unroll
            for (int j = 0; j < 8; j++) {
                int el = j * 8 + d.qc * 2;
                tw[(el    ) * 33 + ml    ] = acc[i][j][0];
                tw[(el + 1) * 33 + ml    ] = acc[i][j][1];
                tw[(el    ) * 33 + ml + 8] = acc[i][j][2];
                tw[(el + 1) * 33 + ml + 8] = acc[i][j][3];
            }
        }
        __syncwarp();
        int b  = (blockIdx.y * TM) >> 11;
        int m0 = (blockIdx.y * TM + d.mw) & (N_ - 1);
        size_t basev = (size_t)(h * B_ + b) * E_ * N_;
        #pragma unroll
        for (int it = 0; it < 16; it++) {
            int el = it * 4 + (d.lane >> 3);
            int m4 = (d.lane & 7) * 4;
            float4 v = make_float4(tw[el*33 + m4], tw[el*33 + m4 + 1],
                                   tw[el*33 + m4 + 2], tw[el*33 + m4 + 3]);
            int e = blockIdx.x * TN + d.nw + el;
            *reinterpret_cast<float4*>(&g_V[basev + (size_t)e * N_ + m0 + m4]) = v;
        }
    }
}

// ---------------------------------------------------------------------------
// Stage 2: scores + exp2 + column sums (softmax over query axis n).
// ---------------------------------------------------------------------------
__global__ void __launch_bounds__(256, 2)
k_scores()
{
    extern __shared__ char dsm[];
    Ids d = make_ids();
    int z = blockIdx.z;
    const float* A  = g_Q + (size_t)z * N_ * E_ + (size_t)blockIdx.y * TM * E_;
    const float* Bm = g_K + (size_t)z * N_ * E_ + (size_t)blockIdx.x * TN * E_;
    float acc[2][8][4] = {};
    mainloop<1>(A, A, A, Bm, Bm, Bm, E_, E_, smem_u32(dsm),
                d.tid, d.mw, d.nw, d.lane, acc);

    const float s2 = 1.4426950408889634f / sqrtf((float)E_);
    float* P  = g_P + (size_t)z * N_ * N_;
    float* Zb = g_Z + (size_t)z * N_;
    float cs0[8], cs1[8];
    #pragma unroll
    for (int j = 0; j < 8; j++) { cs0[j] = 0.f; cs1[j] = 0.f; }
    #pragma unroll
    for (int i = 0; i < 2; i++) {
        size_t r = (size_t)blockIdx.y * TM + d.mw + i * 16 + d.qr;
        #pragma unroll
        for (int j = 0; j < 8; j++) {
            int cn = blockIdx.x * TN + d.nw + j * 8 + d.qc * 2;
            float p0 = rna(exp2f(acc[i][j][0] * s2));
            float p1 = rna(exp2f(acc[i][j][1] * s2));
            float p2 = rna(exp2f(acc[i][j][2] * s2));
            float p3 = rna(exp2f(acc[i][j][3] * s2));
            *reinterpret_cast<float2*>(&P[r * N_ + cn])       = make_float2(p0, p1);
            *reinterpret_cast<float2*>(&P[(r + 8) * N_ + cn]) = make_float2(p2, p3);
            cs0[j] += p0 + p2;
            cs1[j] += p1 + p3;
        }
    }
    #pragma unroll
    for (int j = 0; j < 8; j++) {
        float s0 = cs0[j], s1 = cs1[j];
        #pragma unroll
        for (int o = 4; o < 32; o <<= 1) {
            s0 += __shfl_xor_sync(0xFFFFFFFFu, s0, o);
            s1 += __shfl_xor_sync(0xFFFFFFFFu, s1, o);
        }
        if (d.lane < 4) {
            int cn = blockIdx.x * TN + d.nw + j * 8 + d.lane * 2;
            atomicAdd(&Zb[cn], s0);
            atomicAdd(&Zb[cn + 1], s1);
        }
    }
}

// ---------------------------------------------------------------------------
// Helpers: zero Z; Z -> 1/Z; Vt[hb][e][m] *= invZ[hb][m] (RNA-rounded).
// ---------------------------------------------------------------------------
__global__ void k_zeroZ() {
    int i = blockIdx.x * blockDim.x + threadIdx.x;
    if (i < H_ * B_ * N_) g_Z[i] = 0.0f;
}
__global__ void k_recipZ() {
    int i = blockIdx.x * blockDim.x + threadIdx.x;
    if (i < H_ * B_ * N_) g_Z[i] = 1.0f / g_Z[i];
}
__global__ void k_scaleV() {
    size_t i4 = (size_t)blockIdx.x * blockDim.x + threadIdx.x;
    if (i4 >= (size_t)H_ * B_ * E_ * N_ / 4) return;
    size_t m4 = i4 % (N_ / 4);
    size_t hb = i4 / ((size_t)E_ * N_ / 4);
    float4 v  = *reinterpret_cast<float4*>(g_V + i4 * 4);
    float4 zz = *reinterpret_cast<const float4*>(g_Z + hb * N_ + m4 * 4);
    v.x = rna(v.x * zz.x); v.y = rna(v.y * zz.y);
    v.z = rna(v.z * zz.z); v.w = rna(v.w * zz.w);
    *reinterpret_cast<float4*>(g_V + i4 * 4) = v;
}

// ---------------------------------------------------------------------------
// Stage 4: attn + head-mean. z = b; 3 K-segments (one per head) accumulate.
// ---------------------------------------------------------------------------
__global__ void __launch_bounds__(256, 2)
k_attn()
{
    extern __shared__ char dsm[];
    Ids d = make_ids();
    int b = blockIdx.z;
    const float *Aa[3], *Bb[3];
    #pragma unroll
    for (int h = 0; h < H_; h++) {
        size_t hb = (size_t)(h * B_ + b);
        Aa[h] = g_P + hb * N_ * N_ + (size_t)blockIdx.y * TM * N_;
        Bb[h] = g_V + hb * E_ * N_ + (size_t)blockIdx.x * TN * N_;
    }
    float acc[2][8][4] = {};
    mainloop<3>(Aa[0], Aa[1], Aa[2], Bb[0], Bb[1], Bb[2], N_, N_,
                smem_u32(dsm), d.tid, d.mw, d.nw, d.lane, acc);

    const float inv3 = 1.0f / (float)H_;
    float* C = g_mean + (size_t)b * N_ * E_;
    #pragma unroll
    for (int i = 0; i < 2; i++) {
        size_t r = (size_t)blockIdx.y * TM + d.mw + i * 16 + d.qr;
        #pragma unroll
        for (int j = 0; j < 8; j++) {
            int cn = blockIdx.x * TN + d.nw + j * 8 + d.qc * 2;
            *reinterpret_cast<float2*>(&C[r * E_ + cn]) =
                make_float2(rna(acc[i][j][0] * inv3), rna(acc[i][j][1] * inv3));
            *reinterpret_cast<float2*>(&C[(r + 8) * E_ + cn]) =
                make_float2(rna(acc[i][j][2] * inv3), rna(acc[i][j][3] * inv3));
        }
    }
}

// ---------------------------------------------------------------------------
// Stage 5: out = mean @ fc_w^T + fc_b (bias in full fp32).
// ---------------------------------------------------------------------------
__global__ void __launch_bounds__(256, 2)
k_fc(const float* __restrict__ fc_b, float* __restrict__ out)
{
    extern __shared__ char dsm[];
    Ids d = make_ids();
    const float* A  = g_mean + (size_t)blockIdx.y * TM * E_;
    const float* Bm = g_fcw + (size_t)blockIdx.x * TN * E_;
    float acc[2][8][4] = {};
    mainloop<1>(A, A, A, Bm, Bm, Bm, E_, E_, smem_u32(dsm),
                d.tid, d.mw, d.nw, d.lane, acc);

    #pragma unroll
    for (int i = 0; i < 2; i++) {
        size_t r = (size_t)blockIdx.y * TM + d.mw + i * 16 + d.qr;
        #pragma unroll
        for (int j = 0; j < 8; j++) {
            int cn = blockIdx.x * TN + d.nw + j * 8 + d.qc * 2;
            float2 bia = *reinterpret_cast<const float2*>(&fc_b[cn]);
            *reinterpret_cast<float2*>(&out[r * E_ + cn]) =
                make_float2(acc[i][j][0] + bia.x, acc[i][j][1] + bia.y);
            *reinterpret_cast<float2*>(&out[(r + 8) * E_ + cn]) =
                make_float2(acc[i][j][2] + bia.x, acc[i][j][3] + bia.y);
        }
    }
}

// ---------------------------------------------------------------------------
extern "C" void kernel_launch(void* const* d_in, const int* in_sizes, int n_in,
                              void* d_out, int out_size)
{
    const float* x    = (const float*)d_in[0];
    const float* Wq   = (const float*)d_in[1];
    const float* Wk   = (const float*)d_in[2];
    const float* Wv   = (const float*)d_in[3];
    const float* fc_w = (const float*)d_in[4];
    const float* fc_b = (const float*)d_in[5];
    float* out = (float*)d_out;

    cudaFuncSetAttribute(k_proj,   cudaFuncAttributeMaxDynamicSharedMemorySize, SMEM_GEMM);
    cudaFuncSetAttribute(k_scores, cudaFuncAttributeMaxDynamicSharedMemorySize, SMEM_GEMM);
    cudaFuncSetAttribute(k_attn,   cudaFuncAttributeMaxDynamicSharedMemorySize, SMEM_GEMM);
    cudaFuncSetAttribute(k_fc,     cudaFuncAttributeMaxDynamicSharedMemorySize, SMEM_GEMM);

    const size_t nround = (size_t)MT*E_/4 + 3*(size_t)H_*E_*E_/4 + (size_t)E_*E_/4;
    k_round <<<(int)((nround + 255) / 256), 256>>>(
        (const float4*)x, (const float4*)Wq, (const float4*)Wk,
        (const float4*)Wv, (const float4*)fc_w);
    k_zeroZ <<<(H_*B_*N_ + 255)/256, 256>>>();
    k_proj  <<<dim3(E_/TN, MT/TM, 3*H_), 256, SMEM_GEMM>>>();
    k_scores<<<dim3(N_/TN, N_/TM, H_*B_), 256, SMEM_GEMM>>>();
    k_recipZ<<<(H_*B_*N_ + 255)/256, 256>>>();
    k_scaleV<<<(int)(((size_t)H_*B_*E_*N_/4 + 255)/256), 256>>>();
    k_attn  <<<dim3(E_/TN, N_/TM, B_), 256, SMEM_GEMM>>>();
    k_fc    <<<dim3(E_/TN, MT/TM), 256, SMEM_GEMM>>>(fc_b, out);
}

// round 11
// speedup vs baseline: 9.6685x; 1.9079x over previous
#include <cuda_runtime.h>
#include <cuda_fp16.h>
#include <cstdint>
#include <math.h>

// Problem constants
#define E_ 2048
#define H_ 3
#define B_ 4
#define N_ 2048
#define MT (B_*N_)          // 8192 tokens

// GEMM tile: M=128, N=128, K=64 halfs per chunk; fp16 m16n8k16 HMMA.
// 256 threads (8 warps, 4x2), 3-stage cp.async pipeline, 2 CTAs/SM.
constexpr int TM = 128, TN = 128, TK = 64;
constexpr int STAGES = 3;
constexpr int A_BYTES   = TM * TK * 2;        // 16 KB (128 rows x 128B)
constexpr int B_BYTES   = TN * TK * 2;        // 16 KB
constexpr int BUF_BYTES = A_BYTES + B_BYTES;  // 32 KB
constexpr int SMEM_GEMM = STAGES * BUF_BYTES; // 96 KB
constexpr int CHUNKS_PER_SEG = E_ / TK;       // 32

// Scratch (device globals: allocation-free rule) — fp16 intermediates
__device__ __half g_x  [(size_t)MT*E_];
__device__ __half g_Wq [(size_t)H_*E_*E_];
__device__ __half g_Wk [(size_t)H_*E_*E_];
__device__ __half g_Wv [(size_t)H_*E_*E_];
__device__ __half g_fcw[(size_t)E_*E_];
__device__ __half g_Q[(size_t)H_*B_*N_*E_];   // [h][t][e]
__device__ __half g_K[(size_t)H_*B_*N_*E_];   // [h][t][e]
__device__ __half g_V[(size_t)H_*B_*N_*E_];   // TRANSPOSED [hb][e][m]
__device__ __half g_P[(size_t)H_*B_*N_*N_];   // [hb][n][m] = exp(scores)
__device__ float  g_Z[H_*B_*N_];              // col sums -> 256/Z
__device__ __half g_mean[(size_t)B_*N_*E_];   // [t][e]

// ---------------------------------------------------------------------------
// PTX helpers (plain sm_80+ features only)
// ---------------------------------------------------------------------------
__device__ __forceinline__ uint32_t smem_u32(const void* p) {
    uint32_t a;
    asm("{ .reg .u64 t; cvta.to.shared.u64 t, %1; cvt.u32.u64 %0, t; }"
        : "=r"(a) : "l"(p));
    return a;
}
__device__ __forceinline__ void cp16(uint32_t dst, const void* src) {
    asm volatile("cp.async.cg.shared.global [%0], [%1], 16;" :: "r"(dst), "l"(src));
}
#define CP_COMMIT() asm volatile("cp.async.commit_group;" ::: "memory")
template<int Nw> __device__ __forceinline__ void cp_wait() {
    asm volatile("cp.async.wait_group %0;" :: "n"(Nw) : "memory");
}
__device__ __forceinline__ void ldsm4(uint32_t (&r)[4], uint32_t addr) {
    asm volatile("ldmatrix.sync.aligned.m8n8.x4.shared.b16 {%0,%1,%2,%3}, [%4];"
        : "=r"(r[0]), "=r"(r[1]), "=r"(r[2]), "=r"(r[3]) : "r"(addr));
}
__device__ __forceinline__ void mma_f16(float (&d)[4], const uint32_t (&a)[4],
                                        uint32_t b0, uint32_t b1) {
    asm volatile(
        "mma.sync.aligned.m16n8k16.row.col.f32.f16.f16.f32 "
        "{%0,%1,%2,%3}, {%4,%5,%6,%7}, {%8,%9}, {%0,%1,%2,%3};"
        : "+f"(d[0]), "+f"(d[1]), "+f"(d[2]), "+f"(d[3])
        : "r"(a[0]), "r"(a[1]), "r"(a[2]), "r"(a[3]), "r"(b0), "r"(b1));
}
__device__ __forceinline__ uint32_t pack_h2(float a, float b) {
    __half2 h = __float22half2_rn(make_float2(a, b));
    return *reinterpret_cast<uint32_t*>(&h);
}

// ---------------------------------------------------------------------------
// Prefetch one 128x64 A tile + 128x64 B tile (fp16) via cp.async.
// Row = 64 halfs = 128B = 8 x 16B chunks; chunk c swizzled to c ^ (row&7).
// ---------------------------------------------------------------------------
__device__ __forceinline__ void prefetch_tiles(
    const __half* __restrict__ Ag, const __half* __restrict__ Bg,
    int lda, int ldb, int kt, uint32_t sA, uint32_t sB, int tid)
{
    #pragma unroll
    for (int i = 0; i < 4; i++) {
        int f = tid + i * 256, row = f >> 3, c4 = f & 7;
        cp16(sA + row * 128 + ((c4 ^ (row & 7)) << 4),
             Ag + (size_t)row * lda + kt + c4 * 8);
    }
    #pragma unroll
    for (int i = 0; i < 4; i++) {
        int f = tid + i * 256, row = f >> 3, c4 = f & 7;
        cp16(sB + row * 128 + ((c4 ^ (row & 7)) << 4),
             Bg + (size_t)row * ldb + kt + c4 * 8);
    }
}

// ---------------------------------------------------------------------------
// Compute 128x128 += A(128x64) * B(128x64)^T (fp16) from swizzled smem.
// Warp (mw,nw) owns 32x64. 4 k-steps of k=16 (2 chunks each).
// ---------------------------------------------------------------------------
__device__ __forceinline__ void compute_tiles(
    uint32_t sA, uint32_t sB, int mw, int nw, int lane, float (&acc)[2][8][4])
{
    const int g  = lane >> 3;
    const int i8 = lane & 7;
    const int rA0 = mw + ((g & 1) << 3) + i8;
    const int rB0 = nw + ((g >> 1) << 3) + i8;
    const int chA = (g >> 1), chB = (g & 1);
    #pragma unroll
    for (int kc = 0; kc < 8; kc += 2) {         // 4 k-steps of 16
        uint32_t a[2][4];
        #pragma unroll
        for (int i = 0; i < 2; i++) {
            int row = rA0 + i * 16, ch = kc + chA;
            ldsm4(a[i], sA + row * 128 + ((ch ^ (row & 7)) << 4));
        }
        #pragma unroll
        for (int j2 = 0; j2 < 4; j2++) {
            uint32_t b[4];
            int row = rB0 + j2 * 16, ch = kc + chB;
            ldsm4(b, sB + row * 128 + ((ch ^ (row & 7)) << 4));
            #pragma unroll
            for (int i = 0; i < 2; i++) {
                mma_f16(acc[i][2*j2],   a[i], b[0], b[1]);
                mma_f16(acc[i][2*j2+1], a[i], b[2], b[3]);
            }
        }
    }
}

// ---------------------------------------------------------------------------
// 3-stage cp.async mainloop; NSEG K-segments of 2048 (attn uses 3 heads).
// ---------------------------------------------------------------------------
template<int NSEG>
__device__ __forceinline__ void mainloop(
    const __half* A0, const __half* A1, const __half* A2,
    const __half* B0, const __half* B1, const __half* B2,
    int lda, int ldb, uint32_t sbase, int tid, int mw, int nw, int lane,
    float (&acc)[2][8][4])
{
    const int total = NSEG * CHUNKS_PER_SEG;
    prefetch_tiles(A0, B0, lda, ldb, 0, sbase, sbase + A_BYTES, tid);
    CP_COMMIT();
    prefetch_tiles(A0, B0, lda, ldb, TK, sbase + BUF_BYTES,
                   sbase + BUF_BYTES + A_BYTES, tid);
    CP_COMMIT();
    for (int c = 0; c < total; c++) {
        int cn = c + 2;
        if (cn < total) {
            int s = cn >> 5;
            const __half* Ag = (s == 0) ? A0 : (s == 1 ? A1 : A2);
            const __half* Bg = (s == 0) ? B0 : (s == 1 ? B1 : B2);
            uint32_t off = (uint32_t)(cn % STAGES) * BUF_BYTES;
            prefetch_tiles(Ag, Bg, lda, ldb, (cn & 31) * TK,
                           sbase + off, sbase + off + A_BYTES, tid);
            CP_COMMIT();
            cp_wait<2>();
        } else {
            cp_wait<0>();
        }
        __syncthreads();
        uint32_t off = (uint32_t)(c % STAGES) * BUF_BYTES;
        compute_tiles(sbase + off, sbase + off + A_BYTES, mw, nw, lane, acc);
        __syncthreads();
    }
}

// Common per-thread ids (8 warps: 4 along M, 2 along N)
struct Ids { int tid, lane, wid, mw, nw, qr, qc; };
__device__ __forceinline__ Ids make_ids() {
    Ids d;
    d.tid = threadIdx.x; d.lane = d.tid & 31; d.wid = d.tid >> 5;
    d.mw = (d.wid & 3) * 32; d.nw = (d.wid >> 2) * 64;
    d.qr = d.lane >> 2; d.qc = d.lane & 3;
    return d;
}

// ---------------------------------------------------------------------------
// Stage 0: round inputs to fp16 scratch (x, Wq, Wk, Wv, fc_w). 8 elems/thread.
// ---------------------------------------------------------------------------
__global__ void __launch_bounds__(256)
k_round(const float* __restrict__ x,  const float* __restrict__ Wq,
        const float* __restrict__ Wk, const float* __restrict__ Wv,
        const float* __restrict__ fcw)
{
    const size_t nx = (size_t)MT * E_ / 8, nw = (size_t)H_ * E_ * E_ / 8,
                 nf = (size_t)E_ * E_ / 8;
    size_t i = (size_t)blockIdx.x * blockDim.x + threadIdx.x;
    const float* src; __half* dst; size_t off;
    if      (i < nx)            { src = x;   dst = g_x;   off = i; }
    else if (i < nx + nw)       { src = Wq;  dst = g_Wq;  off = i - nx; }
    else if (i < nx + 2*nw)     { src = Wk;  dst = g_Wk;  off = i - nx - nw; }
    else if (i < nx + 3*nw)     { src = Wv;  dst = g_Wv;  off = i - nx - 2*nw; }
    else if (i < nx + 3*nw + nf){ src = fcw; dst = g_fcw; off = i - nx - 3*nw; }
    else return;
    const float4* s4 = reinterpret_cast<const float4*>(src) + off * 2;
    float4 a = s4[0], b = s4[1];
    uint4 u;
    u.x = pack_h2(a.x, a.y); u.y = pack_h2(a.z, a.w);
    u.z = pack_h2(b.x, b.y); u.w = pack_h2(b.z, b.w);
    reinterpret_cast<uint4*>(dst)[off] = u;
}

// ---------------------------------------------------------------------------
// Stage 1: projections. z: t=z/3 (Q,K,V), h=z%3. C = x @ W[h]^T.
// Q,K row-major fp16; V stored TRANSPOSED [hb][e][m] via smem transpose.
// ---------------------------------------------------------------------------
__global__ void __launch_bounds__(256, 2)
k_proj()
{
    extern __shared__ char dsm[];
    Ids d = make_ids();
    int z = blockIdx.z, t = z / H_, h = z - t * H_;
    const __half* W = (t == 0 ? g_Wq : (t == 1 ? g_Wk : g_Wv)) + (size_t)h * E_ * E_;
    const __half* A  = g_x + (size_t)blockIdx.y * TM * E_;
    const __half* Bm = W + (size_t)blockIdx.x * TN * E_;
    float acc[2][8][4] = {};
    mainloop<1>(A, A, A, Bm, Bm, Bm, E_, E_, smem_u32(dsm),
                d.tid, d.mw, d.nw, d.lane, acc);

    if (t < 2) {
        __half* C = (t == 0 ? g_Q : g_K) + (size_t)h * MT * E_;
        #pragma unroll
        for (int i = 0; i < 2; i++) {
            size_t r = (size_t)blockIdx.y * TM + d.mw + i * 16 + d.qr;
            #pragma unroll
            for (int j = 0; j < 8; j++) {
                int cn = blockIdx.x * TN + d.nw + j * 8 + d.qc * 2;
                *reinterpret_cast<uint32_t*>(&C[r * E_ + cn]) =
                    pack_h2(acc[i][j][0], acc[i][j][1]);
                *reinterpret_cast<uint32_t*>(&C[(r + 8) * E_ + cn]) =
                    pack_h2(acc[i][j][2], acc[i][j][3]);
            }
        }
    } else {
        // transpose 32x64 warp tile through smem, write coalesced Vt rows
        float* tw = reinterpret_cast<float*>(dsm) + d.wid * 2112;  // [64][33]
        #pragma unroll
        for (int i = 0; i < 2; i++) {
            int ml = i * 16 + d.qr;
            #pragma unroll
            for (int j = 0; j < 8; j++) {
                int el = j * 8 + d.qc * 2;
                tw[(el    ) * 33 + ml    ] = acc[i][j][0];
                tw[(el + 1) * 33 + ml    ] = acc[i][j][1];
                tw[(el    ) * 33 + ml + 8] = acc[i][j][2];
                tw[(el + 1) * 33 + ml + 8] = acc[i][j][3];
            }
        }
        __syncwarp();
        int b  = (blockIdx.y * TM) >> 11;
        int m0 = (blockIdx.y * TM + d.mw) & (N_ - 1);
        size_t basev = (size_t)(h * B_ + b) * E_ * N_;
        #pragma unroll
        for (int it = 0; it < 8; it++) {          // 8 e-rows/iter, 8 halfs/lane
            int el = it * 8 + (d.lane >> 2);
            int m8 = (d.lane & 3) * 8;
            const float* tr = &tw[el * 33 + m8];
            uint4 u;
            u.x = pack_h2(tr[0], tr[1]); u.y = pack_h2(tr[2], tr[3]);
            u.z = pack_h2(tr[4], tr[5]); u.w = pack_h2(tr[6], tr[7]);
            int e = blockIdx.x * TN + d.nw + el;
            *reinterpret_cast<uint4*>(&g_V[basev + (size_t)e * N_ + m0 + m8]) = u;
        }
    }
}

// ---------------------------------------------------------------------------
// Stage 2: scores + exp2 + column sums (softmax over query axis n).
// Sums accumulate the fp16-ROUNDED values so Z matches what attn-GEMM reads.
// ---------------------------------------------------------------------------
__global__ void __launch_bounds__(256, 2)
k_scores()
{
    extern __shared__ char dsm[];
    Ids d = make_ids();
    int z = blockIdx.z;
    const __half* A  = g_Q + (size_t)z * N_ * E_ + (size_t)blockIdx.y * TM * E_;
    const __half* Bm = g_K + (size_t)z * N_ * E_ + (size_t)blockIdx.x * TN * E_;
    float acc[2][8][4] = {};
    mainloop<1>(A, A, A, Bm, Bm, Bm, E_, E_, smem_u32(dsm),
                d.tid, d.mw, d.nw, d.lane, acc);

    const float s2 = 1.4426950408889634f / sqrtf((float)E_);
    __half* P = g_P + (size_t)z * N_ * N_;
    float* Zb = g_Z + (size_t)z * N_;
    float cs0[8], cs1[8];
    #pragma unroll
    for (int j = 0; j < 8; j++) { cs0[j] = 0.f; cs1[j] = 0.f; }
    #pragma unroll
    for (int i = 0; i < 2; i++) {
        size_t r = (size_t)blockIdx.y * TM + d.mw + i * 16 + d.qr;
        #pragma unroll
        for (int j = 0; j < 8; j++) {
            int cn = blockIdx.x * TN + d.nw + j * 8 + d.qc * 2;
            __half2 h0 = __float22half2_rn(make_float2(
                exp2f(acc[i][j][0] * s2), exp2f(acc[i][j][1] * s2)));
            __half2 h1 = __float22half2_rn(make_float2(
                exp2f(acc[i][j][2] * s2), exp2f(acc[i][j][3] * s2)));
            *reinterpret_cast<__half2*>(&P[r * N_ + cn])       = h0;
            *reinterpret_cast<__half2*>(&P[(r + 8) * N_ + cn]) = h1;
            float2 f0 = __half22float2(h0), f1 = __half22float2(h1);
            cs0[j] += f0.x + f1.x;
            cs1[j] += f0.y + f1.y;
        }
    }
    #pragma unroll
    for (int j = 0; j < 8; j++) {
        float s0 = cs0[j], s1 = cs1[j];
        #pragma unroll
        for (int o = 4; o < 32; o <<= 1) {
            s0 += __shfl_xor_sync(0xFFFFFFFFu, s0, o);
            s1 += __shfl_xor_sync(0xFFFFFFFFu, s1, o);
        }
        if (d.lane < 4) {
            int cn = blockIdx.x * TN + d.nw + j * 8 + d.lane * 2;
            atomicAdd(&Zb[cn], s0);
            atomicAdd(&Zb[cn + 1], s1);
        }
    }
}

// ---------------------------------------------------------------------------
// Helpers: zero Z; Z -> 256/Z (x256 keeps scaled V out of fp16 subnormals;
// compensated by 1/(3*256) in the attn epilogue); Vt *= scaled invZ.
// ---------------------------------------------------------------------------
__global__ void k_zeroZ() {
    int i = blockIdx.x * blockDim.x + threadIdx.x;
    if (i < H_ * B_ * N_) g_Z[i] = 0.0f;
}
__global__ void k_recipZ() {
    int i = blockIdx.x * blockDim.x + threadIdx.x;
    if (i < H_ * B_ * N_) g_Z[i] = 256.0f / g_Z[i];
}
__global__ void __launch_bounds__(256)
k_scaleV() {
    size_t i8 = (size_t)blockIdx.x * blockDim.x + threadIdx.x;   // 8 halfs each
    if (i8 >= (size_t)H_ * B_ * E_ * N_ / 8) return;
    size_t m8 = (i8 % (N_ / 8)) * 8;
    size_t hb = i8 / ((size_t)E_ * N_ / 8);
    uint4 u = reinterpret_cast<uint4*>(g_V)[i8];
    const float* zz = g_Z + hb * N_ + m8;
    float2 v0 = __half22float2(*reinterpret_cast<__half2*>(&u.x));
    float2 v1 = __half22float2(*reinterpret_cast<__half2*>(&u.y));
    float2 v2 = __half22float2(*reinterpret_cast<__half2*>(&u.z));
    float2 v3 = __half22float2(*reinterpret_cast<__half2*>(&u.w));
    u.x = pack_h2(v0.x * zz[0], v0.y * zz[1]);
    u.y = pack_h2(v1.x * zz[2], v1.y * zz[3]);
    u.z = pack_h2(v2.x * zz[4], v2.y * zz[5]);
    u.w = pack_h2(v3.x * zz[6], v3.y * zz[7]);
    reinterpret_cast<uint4*>(g_V)[i8] = u;
}

// ---------------------------------------------------------------------------
// Stage 4: attn + head-mean. z = b; 3 K-segments (one per head) accumulate.
// ---------------------------------------------------------------------------
__global__ void __launch_bounds__(256, 2)
k_attn()
{
    extern __shared__ char dsm[];
    Ids d = make_ids();
    int b = blockIdx.z;
    const __half *Aa[3], *Bb[3];
    #pragma unroll
    for (int h = 0; h < H_; h++) {
        size_t hb = (size_t)(h * B_ + b);
        Aa[h] = g_P + hb * N_ * N_ + (size_t)blockIdx.y * TM * N_;
        Bb[h] = g_V + hb * E_ * N_ + (size_t)blockIdx.x * TN * N_;
    }
    float acc[2][8][4] = {};
    mainloop<3>(Aa[0], Aa[1], Aa[2], Bb[0], Bb[1], Bb[2], N_, N_,
                smem_u32(dsm), d.tid, d.mw, d.nw, d.lane, acc);

    const float sc = 1.0f / (3.0f * 256.0f);    // head-mean + invZ x256 comp
    __half* C = g_mean + (size_t)b * N_ * E_;
    #pragma unroll
    for (int i = 0; i < 2; i++) {
        size_t r = (size_t)blockIdx.y * TM + d.mw + i * 16 + d.qr;
        #pragma unroll
        for (int j = 0; j < 8; j++) {
            int cn = blockIdx.x * TN + d.nw + j * 8 + d.qc * 2;
            *reinterpret_cast<uint32_t*>(&C[r * E_ + cn]) =
                pack_h2(acc[i][j][0] * sc, acc[i][j][1] * sc);
            *reinterpret_cast<uint32_t*>(&C[(r + 8) * E_ + cn]) =
                pack_h2(acc[i][j][2] * sc, acc[i][j][3] * sc);
        }
    }
}

// ---------------------------------------------------------------------------
// Stage 5: out = mean @ fc_w^T + fc_b (bias + output in full fp32).
// ---------------------------------------------------------------------------
__global__ void __launch_bounds__(256, 2)
k_fc(const float* __restrict__ fc_b, float* __restrict__ out)
{
    extern __shared__ char dsm[];
    Ids d = make_ids();
    const __half* A  = g_mean + (size_t)blockIdx.y * TM * E_;
    const __half* Bm = g_fcw + (size_t)blockIdx.x * TN * E_;
    float acc[2][8][4] = {};
    mainloop<1>(A, A, A, Bm, Bm, Bm, E_, E_, smem_u32(dsm),
                d.tid, d.mw, d.nw, d.lane, acc);

    #pragma unroll
    for (int i = 0; i < 2; i++) {
        size_t r = (size_t)blockIdx.y * TM + d.mw + i * 16 + d.qr;
        #pragma unroll
        for (int j = 0; j < 8; j++) {
            int cn = blockIdx.x * TN + d.nw + j * 8 + d.qc * 2;
            float2 bia = *reinterpret_cast<const float2*>(&fc_b[cn]);
            *reinterpret_cast<float2*>(&out[r * E_ + cn]) =
                make_float2(acc[i][j][0] + bia.x, acc[i][j][1] + bia.y);
            *reinterpret_cast<float2*>(&out[(r + 8) * E_ + cn]) =
                make_float2(acc[i][j][2] + bia.x, acc[i][j][3] + bia.y);
        }
    }
}

// ---------------------------------------------------------------------------
extern "C" void kernel_launch(void* const* d_in, const int* in_sizes, int n_in,
                              void* d_out, int out_size)
{
    const float* x    = (const float*)d_in[0];
    const float* Wq   = (const float*)d_in[1];
    const float* Wk   = (const float*)d_in[2];
    const float* Wv   = (const float*)d_in[3];
    const float* fc_w = (const float*)d_in[4];
    const float* fc_b = (const float*)d_in[5];
    float* out = (float*)d_out;

    cudaFuncSetAttribute(k_proj,   cudaFuncAttributeMaxDynamicSharedMemorySize, SMEM_GEMM);
    cudaFuncSetAttribute(k_scores, cudaFuncAttributeMaxDynamicSharedMemorySize, SMEM_GEMM);
    cudaFuncSetAttribute(k_attn,   cudaFuncAttributeMaxDynamicSharedMemorySize, SMEM_GEMM);
    cudaFuncSetAttribute(k_fc,     cudaFuncAttributeMaxDynamicSharedMemorySize, SMEM_GEMM);

    const size_t nround = (size_t)MT*E_/8 + 3*(size_t)H_*E_*E_/8 + (size_t)E_*E_/8;
    k_round <<<(int)((nround + 255) / 256), 256>>>(x, Wq, Wk, Wv, fc_w);
    k_zeroZ <<<(H_*B_*N_ + 255)/256, 256>>>();
    k_proj  <<<dim3(E_/TN, MT/TM, 3*H_), 256, SMEM_GEMM>>>();
    k_scores<<<dim3(N_/TN, N_/TM, H_*B_), 256, SMEM_GEMM>>>();
    k_recipZ<<<(H_*B_*N_ + 255)/256, 256>>>();
    k_scaleV<<<(int)(((size_t)H_*B_*E_*N_/8 + 255)/256), 256>>>();
    k_attn  <<<dim3(E_/TN, N_/TM, B_), 256, SMEM_GEMM>>>();
    k_fc    <<<dim3(E_/TN, MT/TM), 256, SMEM_GEMM>>>(fc_b, out);
}

// round 13
// speedup vs baseline: 10.6838x; 1.1050x over previous
#include <cuda_runtime.h>
#include <cuda_fp16.h>
#include <cstdint>
#include <math.h>

// Problem constants
#define E_ 2048
#define H_ 3
#define B_ 4
#define N_ 2048
#define MT (B_*N_)          // 8192 tokens

// GEMM tile: M=128, N=128, K=64 halfs per chunk; fp16 m16n8k16 HMMA.
// 256 threads (8 warps, 4x2), 3-stage cp.async ring, ONE barrier per chunk.
constexpr int TM = 128, TN = 128, TK = 64;
constexpr int STAGES = 3;
constexpr int A_BYTES   = TM * TK * 2;        // 16 KB (128 rows x 128B)
constexpr int B_BYTES   = TN * TK * 2;        // 16 KB
constexpr int BUF_BYTES = A_BYTES + B_BYTES;  // 32 KB
constexpr int SMEM_GEMM = STAGES * BUF_BYTES; // 96 KB
constexpr int CHUNKS_PER_SEG = E_ / TK;       // 32

// Scratch (device globals: allocation-free rule) — fp16 intermediates
__device__ __half g_x  [(size_t)MT*E_];
__device__ __half g_Wq [(size_t)H_*E_*E_];
__device__ __half g_Wk [(size_t)H_*E_*E_];
__device__ __half g_Wv [(size_t)H_*E_*E_];
__device__ __half g_fcw[(size_t)E_*E_];
__device__ __half g_WqT[(size_t)H_*E_*E_];    // [h][e][d] transposed weights
__device__ __half g_WkT[(size_t)H_*E_*E_];
__device__ __half g_M  [(size_t)H_*E_*E_];    // Mt[h][e'][e] = sum_d Wk[d,e']Wq[d,e]
__device__ __half g_R  [(size_t)H_*MT*E_];    // R[h][t][e'] = x @ Mt^T
__device__ __half g_V  [(size_t)H_*B_*N_*E_]; // TRANSPOSED [hb][e][m]
__device__ __half g_P  [(size_t)H_*B_*N_*N_]; // [hb][n][m] = exp(scores)
__device__ float  g_Z  [H_*B_*N_];            // col sums -> 256/Z
__device__ __half g_mean[(size_t)B_*N_*E_];   // [t][e]

// ---------------------------------------------------------------------------
// PTX helpers (plain sm_80+ features only)
// ---------------------------------------------------------------------------
__device__ __forceinline__ uint32_t smem_u32(const void* p) {
    uint32_t a;
    asm("{ .reg .u64 t; cvta.to.shared.u64 t, %1; cvt.u32.u64 %0, t; }"
        : "=r"(a) : "l"(p));
    return a;
}
__device__ __forceinline__ void cp16(uint32_t dst, const void* src) {
    asm volatile("cp.async.cg.shared.global [%0], [%1], 16;" :: "r"(dst), "l"(src));
}
#define CP_COMMIT() asm volatile("cp.async.commit_group;" ::: "memory")
template<int Nw> __device__ __forceinline__ void cp_wait() {
    asm volatile("cp.async.wait_group %0;" :: "n"(Nw) : "memory");
}
__device__ __forceinline__ void ldsm4(uint32_t (&r)[4], uint32_t addr) {
    asm volatile("ldmatrix.sync.aligned.m8n8.x4.shared.b16 {%0,%1,%2,%3}, [%4];"
        : "=r"(r[0]), "=r"(r[1]), "=r"(r[2]), "=r"(r[3]) : "r"(addr));
}
__device__ __forceinline__ void mma_f16(float (&d)[4], const uint32_t (&a)[4],
                                        uint32_t b0, uint32_t b1) {
    asm volatile(
        "mma.sync.aligned.m16n8k16.row.col.f32.f16.f16.f32 "
        "{%0,%1,%2,%3}, {%4,%5,%6,%7}, {%8,%9}, {%0,%1,%2,%3};"
        : "+f"(d[0]), "+f"(d[1]), "+f"(d[2]), "+f"(d[3])
        : "r"(a[0]), "r"(a[1]), "r"(a[2]), "r"(a[3]), "r"(b0), "r"(b1));
}
__device__ __forceinline__ uint32_t pack_h2(float a, float b) {
    __half2 h = __float22half2_rn(make_float2(a, b));
    return *reinterpret_cast<uint32_t*>(&h);
}

// ---------------------------------------------------------------------------
// Prefetch one 128x64 A tile + 128x64 B tile (fp16) via cp.async.
// Row = 64 halfs = 128B = 8 x 16B chunks; chunk c swizzled to c ^ (row&7).
// ---------------------------------------------------------------------------
__device__ __forceinline__ void prefetch_tiles(
    const __half* __restrict__ Ag, const __half* __restrict__ Bg,
    int lda, int ldb, int kt, uint32_t sA, uint32_t sB, int tid)
{
    #pragma unroll
    for (int i = 0; i < 4; i++) {
        int f = tid + i * 256, row = f >> 3, c4 = f & 7;
        cp16(sA + row * 128 + ((c4 ^ (row & 7)) << 4),
             Ag + (size_t)row * lda + kt + c4 * 8);
    }
    #pragma unroll
    for (int i = 0; i < 4; i++) {
        int f = tid + i * 256, row = f >> 3, c4 = f & 7;
        cp16(sB + row * 128 + ((c4 ^ (row & 7)) << 4),
             Bg + (size_t)row * ldb + kt + c4 * 8);
    }
}

// ---------------------------------------------------------------------------
// Compute 128x128 += A(128x64) * B(128x64)^T (fp16) from swizzled smem.
// Warp (mw,nw) owns 32x64. 4 k-steps of k=16 (2 chunks each).
// ---------------------------------------------------------------------------
__device__ __forceinline__ void compute_tiles(
    uint32_t sA, uint32_t sB, int mw, int nw, int lane, float (&acc)[2][8][4])
{
    const int g  = lane >> 3;
    const int i8 = lane & 7;
    const int rA0 = mw + ((g & 1) << 3) + i8;
    const int rB0 = nw + ((g >> 1) << 3) + i8;
    const int chA = (g >> 1), chB = (g & 1);
    #pragma unroll
    for (int kc = 0; kc < 8; kc += 2) {         // 4 k-steps of 16
        uint32_t a[2][4];
        #pragma unroll
        for (int i = 0; i < 2; i++) {
            int row = rA0 + i * 16, ch = kc + chA;
            ldsm4(a[i], sA + row * 128 + ((ch ^ (row & 7)) << 4));
        }
        #pragma unroll
        for (int j2 = 0; j2 < 4; j2++) {
            uint32_t b[4];
            int row = rB0 + j2 * 16, ch = kc + chB;
            ldsm4(b, sB + row * 128 + ((ch ^ (row & 7)) << 4));
            #pragma unroll
            for (int i = 0; i < 2; i++) {
                mma_f16(acc[i][2*j2],   a[i], b[0], b[1]);
                mma_f16(acc[i][2*j2+1], a[i], b[2], b[3]);
            }
        }
    }
}

// ---------------------------------------------------------------------------
// 3-stage cp.async mainloop with ONE barrier per chunk.
// Prefetch of chunk c+2 targets buffer (c+2)%3 == (c-1)%3; the barrier at
// iteration c proves all threads finished compute(c-1), so the write is safe.
// NSEG K-segments of 2048 (attn uses 3 heads).
// ---------------------------------------------------------------------------
template<int NSEG>
__device__ __forceinline__ void mainloop(
    const __half* A0, const __half* A1, const __half* A2,
    const __half* B0, const __half* B1, const __half* B2,
    int lda, int ldb, uint32_t sbase, int tid, int mw, int nw, int lane,
    float (&acc)[2][8][4])
{
    const int total = NSEG * CHUNKS_PER_SEG;
    prefetch_tiles(A0, B0, lda, ldb, 0, sbase, sbase + A_BYTES, tid);
    CP_COMMIT();
    prefetch_tiles(A0, B0, lda, ldb, TK, sbase + BUF_BYTES,
                   sbase + BUF_BYTES + A_BYTES, tid);
    CP_COMMIT();
    for (int c = 0; c < total; c++) {
        if (c + 1 < total) cp_wait<1>(); else cp_wait<0>();
        __syncthreads();
        int cn = c + 2;
        if (cn < total) {
            int s = cn >> 5;
            const __half* Ag = (s == 0) ? A0 : (s == 1 ? A1 : A2);
            const __half* Bg = (s == 0) ? B0 : (s == 1 ? B1 : B2);
            uint32_t off = (uint32_t)(cn % STAGES) * BUF_BYTES;
            prefetch_tiles(Ag, Bg, lda, ldb, (cn & 31) * TK,
                           sbase + off, sbase + off + A_BYTES, tid);
            CP_COMMIT();
        }
        uint32_t off = (uint32_t)(c % STAGES) * BUF_BYTES;
        compute_tiles(sbase + off, sbase + off + A_BYTES, mw, nw, lane, acc);
    }
}

// Common per-thread ids (8 warps: 4 along M, 2 along N)
struct Ids { int tid, lane, wid, mw, nw, qr, qc; };
__device__ __forceinline__ Ids make_ids() {
    Ids d;
    d.tid = threadIdx.x; d.lane = d.tid & 31; d.wid = d.tid >> 5;
    d.mw = (d.wid & 3) * 32; d.nw = (d.wid >> 2) * 64;
    d.qr = d.lane >> 2; d.qc = d.lane & 3;
    return d;
}

// Shared fp16 row-major epilogue: write acc (2x8x4) to C[row][col] halves.
__device__ __forceinline__ void store_half_tile(
    __half* C, int ldc, const Ids& d, int by, int bx, float (&acc)[2][8][4])
{
    #pragma unroll
    for (int i = 0; i < 2; i++) {
        size_t r = (size_t)by * TM + d.mw + i * 16 + d.qr;
        #pragma unroll
        for (int j = 0; j < 8; j++) {
            int cn = bx * TN + d.nw + j * 8 + d.qc * 2;
            *reinterpret_cast<uint32_t*>(&C[r * ldc + cn]) =
                pack_h2(acc[i][j][0], acc[i][j][1]);
            *reinterpret_cast<uint32_t*>(&C[(r + 8) * ldc + cn]) =
                pack_h2(acc[i][j][2], acc[i][j][3]);
        }
    }
}

// ---------------------------------------------------------------------------
// Stage 0a: round inputs to fp16 scratch (x, Wq, Wk, Wv, fc_w).
// ---------------------------------------------------------------------------
__global__ void __launch_bounds__(256)
k_round(const float* __restrict__ x,  const float* __restrict__ Wq,
        const float* __restrict__ Wk, const float* __restrict__ Wv,
        const float* __restrict__ fcw)
{
    const size_t nx = (size_t)MT * E_ / 8, nw = (size_t)H_ * E_ * E_ / 8,
                 nf = (size_t)E_ * E_ / 8;
    size_t i = (size_t)blockIdx.x * blockDim.x + threadIdx.x;
    const float* src; __half* dst; size_t off;
    if      (i < nx)            { src = x;   dst = g_x;   off = i; }
    else if (i < nx + nw)       { src = Wq;  dst = g_Wq;  off = i - nx; }
    else if (i < nx + 2*nw)     { src = Wk;  dst = g_Wk;  off = i - nx - nw; }
    else if (i < nx + 3*nw)     { src = Wv;  dst = g_Wv;  off = i - nx - 2*nw; }
    else if (i < nx + 3*nw + nf){ src = fcw; dst = g_fcw; off = i - nx - 3*nw; }
    else return;
    const float4* s4 = reinterpret_cast<const float4*>(src) + off * 2;
    float4 a = s4[0], b = s4[1];
    uint4 u;
    u.x = pack_h2(a.x, a.y); u.y = pack_h2(a.z, a.w);
    u.z = pack_h2(b.x, b.y); u.w = pack_h2(b.z, b.w);
    reinterpret_cast<uint4*>(dst)[off] = u;
}

// ---------------------------------------------------------------------------
// Stage 0b: transpose Wq, Wk (fp16): [h][d][e] -> [h][e][d]. 64x64 tiles.
// ---------------------------------------------------------------------------
__global__ void __launch_bounds__(256)
k_transW()
{
    __shared__ __half s[64][72];     // 144B row stride (16B aligned)
    int z = blockIdx.z;
    const __half* src = (z < H_ ? g_Wq : g_Wk) + (size_t)(z % H_) * E_ * E_;
    __half*       dst = (z < H_ ? g_WqT : g_WkT) + (size_t)(z % H_) * E_ * E_;
    int d0 = blockIdx.y * 64, e0 = blockIdx.x * 64;
    int tid = threadIdx.x;
    #pragma unroll
    for (int i = 0; i < 2; i++) {
        int f = tid + i * 256, r = f >> 3, c8 = (f & 7) * 8;
        uint4 u = *reinterpret_cast<const uint4*>(&src[(size_t)(d0 + r) * E_ + e0 + c8]);
        *reinterpret_cast<uint4*>(&s[r][c8]) = u;
    }
    __syncthreads();
    #pragma unroll
    for (int i = 0; i < 2; i++) {
        int f = tid + i * 256, r = f >> 3, c8 = (f & 7) * 8;
        __half t[8];
        #pragma unroll
        for (int j = 0; j < 8; j++) t[j] = s[c8 + j][r];
        *reinterpret_cast<uint4*>(&dst[(size_t)(e0 + r) * E_ + d0 + c8]) =
            *reinterpret_cast<uint4*>(t);
    }
}

// ---------------------------------------------------------------------------
// Stage 1: Mt_h = WkT_h @ (WqT_h)^T  (E x E per head, 25.8 GMAC total).
// Mt[e'][e] = sum_d Wk[d,e'] Wq[d,e].
// ---------------------------------------------------------------------------
__global__ void __launch_bounds__(256, 2)
k_wgemmM()
{
    extern __shared__ char dsm[];
    Ids d = make_ids();
    int h = blockIdx.z;
    const __half* A  = g_WkT + (size_t)h * E_ * E_ + (size_t)blockIdx.y * TM * E_;
    const __half* Bm = g_WqT + (size_t)h * E_ * E_ + (size_t)blockIdx.x * TN * E_;
    float acc[2][8][4] = {};
    mainloop<1>(A, A, A, Bm, Bm, Bm, E_, E_, smem_u32(dsm),
                d.tid, d.mw, d.nw, d.lane, acc);
    store_half_tile(g_M + (size_t)h * E_ * E_, E_, d, blockIdx.y, blockIdx.x, acc);
}

// ---------------------------------------------------------------------------
// Stage 2: R_h = x @ Mt_h^T  ([MT, E] per head, 103 GMAC).
// ---------------------------------------------------------------------------
__global__ void __launch_bounds__(256, 2)
k_R()
{
    extern __shared__ char dsm[];
    Ids d = make_ids();
    int h = blockIdx.z;
    const __half* A  = g_x + (size_t)blockIdx.y * TM * E_;
    const __half* Bm = g_M + (size_t)h * E_ * E_ + (size_t)blockIdx.x * TN * E_;
    float acc[2][8][4] = {};
    mainloop<1>(A, A, A, Bm, Bm, Bm, E_, E_, smem_u32(dsm),
                d.tid, d.mw, d.nw, d.lane, acc);
    store_half_tile(g_R + (size_t)h * MT * E_, E_, d, blockIdx.y, blockIdx.x, acc);
}

// ---------------------------------------------------------------------------
// Stage 3: V projection only: V = x @ Wv_h^T, stored TRANSPOSED [hb][e][m].
// ---------------------------------------------------------------------------
__global__ void __launch_bounds__(256, 2)
k_projV()
{
    extern __shared__ char dsm[];
    Ids d = make_ids();
    int h = blockIdx.z;
    const __half* A  = g_x + (size_t)blockIdx.y * TM * E_;
    const __half* Bm = g_Wv + (size_t)h * E_ * E_ + (size_t)blockIdx.x * TN * E_;
    float acc[2][8][4] = {};
    mainloop<1>(A, A, A, Bm, Bm, Bm, E_, E_, smem_u32(dsm),
                d.tid, d.mw, d.nw, d.lane, acc);

    __syncthreads();   // stage buffers may still be read by lagging warps; tw overlaps them
    // transpose 32x64 warp tile through smem, write coalesced Vt rows
    float* tw = reinterpret_cast<float*>(dsm) + d.wid * 2112;  // [64][33]
    #pragma unroll
    for (int i = 0; i < 2; i++) {
        int ml = i * 16 + d.qr;
        #pragma unroll
        for (int j = 0; j < 8; j++) {
            int el = j * 8 + d.qc * 2;
            tw[(el    ) * 33 + ml    ] = acc[i][j][0];
            tw[(el + 1) * 33 + ml    ] = acc[i][j][1];
            tw[(el    ) * 33 + ml + 8] = acc[i][j][2];
            tw[(el + 1) * 33 + ml + 8] = acc[i][j][3];
        }
    }
    __syncwarp();
    int b  = (blockIdx.y * TM) >> 11;
    int m0 = (blockIdx.y * TM + d.mw) & (N_ - 1);
    size_t basev = (size_t)(h * B_ + b) * E_ * N_;
    #pragma unroll
    for (int it = 0; it < 8; it++) {          // 8 e-rows/iter, 8 halfs/lane
        int el = it * 8 + (d.lane >> 2);
        int m8 = (d.lane & 3) * 8;
        const float* tr = &tw[el * 33 + m8];
        uint4 u;
        u.x = pack_h2(tr[0], tr[1]); u.y = pack_h2(tr[2], tr[3]);
        u.z = pack_h2(tr[4], tr[5]); u.w = pack_h2(tr[6], tr[7]);
        int e = blockIdx.x * TN + d.nw + el;
        *reinterpret_cast<uint4*>(&g_V[basev + (size_t)e * N_ + m0 + m8]) = u;
    }
}

// ---------------------------------------------------------------------------
// Stage 4: scores + exp2 + column sums. P = exp2(s2 * R_hb @ x_b^T).
// Sums accumulate the fp16-ROUNDED values so Z matches what attn-GEMM reads.
// ---------------------------------------------------------------------------
__global__ void __launch_bounds__(256, 2)
k_scores()
{
    extern __shared__ char dsm[];
    Ids d = make_ids();
    int z = blockIdx.z;                     // z = h*B + b
    const __half* A  = g_R + (size_t)z * N_ * E_ + (size_t)blockIdx.y * TM * E_;
    const __half* Bm = g_x + (size_t)(z % B_) * N_ * E_ + (size_t)blockIdx.x * TN * E_;
    float acc[2][8][4] = {};
    mainloop<1>(A, A, A, Bm, Bm, Bm, E_, E_, smem_u32(dsm),
                d.tid, d.mw, d.nw, d.lane, acc);

    const float s2 = 1.4426950408889634f / sqrtf((float)E_);
    __half* P = g_P + (size_t)z * N_ * N_;
    float* Zb = g_Z + (size_t)z * N_;
    float cs0[8], cs1[8];
    #pragma unroll
    for (int j = 0; j < 8; j++) { cs0[j] = 0.f; cs1[j] = 0.f; }
    #pragma unroll
    for (int i = 0; i < 2; i++) {
        size_t r = (size_t)blockIdx.y * TM + d.mw + i * 16 + d.qr;
        #pragma unroll
        for (int j = 0; j < 8; j++) {
            int cn = blockIdx.x * TN + d.nw + j * 8 + d.qc * 2;
            __half2 h0 = __float22half2_rn(make_float2(
                exp2f(acc[i][j][0] * s2), exp2f(acc[i][j][1] * s2)));
            __half2 h1 = __float22half2_rn(make_float2(
                exp2f(acc[i][j][2] * s2), exp2f(acc[i][j][3] * s2)));
            *reinterpret_cast<__half2*>(&P[r * N_ + cn])       = h0;
            *reinterpret_cast<__half2*>(&P[(r + 8) * N_ + cn]) = h1;
            float2 f0 = __half22float2(h0), f1 = __half22float2(h1);
            cs0[j] += f0.x + f1.x;
            cs1[j] += f0.y + f1.y;
        }
    }
    #pragma unroll
    for (int j = 0; j < 8; j++) {
        float s0 = cs0[j], s1 = cs1[j];
        #pragma unroll
        for (int o = 4; o < 32; o <<= 1) {
            s0 += __shfl_xor_sync(0xFFFFFFFFu, s0, o);
            s1 += __shfl_xor_sync(0xFFFFFFFFu, s1, o);
        }
        if (d.lane < 4) {
            int cn = blockIdx.x * TN + d.nw + j * 8 + d.lane * 2;
            atomicAdd(&Zb[cn], s0);
            atomicAdd(&Zb[cn + 1], s1);
        }
    }
}

// ---------------------------------------------------------------------------
// Helpers: zero Z; Z -> 256/Z (x256 keeps scaled V out of fp16 subnormals;
// compensated by 1/(3*256) in the attn epilogue); Vt *= scaled invZ.
// ---------------------------------------------------------------------------
__global__ void k_zeroZ() {
    int i = blockIdx.x * blockDim.x + threadIdx.x;
    if (i < H_ * B_ * N_) g_Z[i] = 0.0f;
}
__global__ void k_recipZ() {
    int i = blockIdx.x * blockDim.x + threadIdx.x;
    if (i < H_ * B_ * N_) g_Z[i] = 256.0f / g_Z[i];
}
__global__ void __launch_bounds__(256)
k_scaleV() {
    size_t i8 = (size_t)blockIdx.x * blockDim.x + threadIdx.x;   // 8 halfs each
    if (i8 >= (size_t)H_ * B_ * E_ * N_ / 8) return;
    size_t m8 = (i8 % (N_ / 8)) * 8;
    size_t hb = i8 / ((size_t)E_ * N_ / 8);
    uint4 u = reinterpret_cast<uint4*>(g_V)[i8];
    const float* zz = g_Z + hb * N_ + m8;
    float2 v0 = __half22float2(*reinterpret_cast<__half2*>(&u.x));
    float2 v1 = __half22float2(*reinterpret_cast<__half2*>(&u.y));
    float2 v2 = __half22float2(*reinterpret_cast<__half2*>(&u.z));
    float2 v3 = __half22float2(*reinterpret_cast<__half2*>(&u.w));
    u.x = pack_h2(v0.x * zz[0], v0.y * zz[1]);
    u.y = pack_h2(v1.x * zz[2], v1.y * zz[3]);
    u.z = pack_h2(v2.x * zz[4], v2.y * zz[5]);
    u.w = pack_h2(v3.x * zz[6], v3.y * zz[7]);
    reinterpret_cast<uint4*>(g_V)[i8] = u;
}

// ---------------------------------------------------------------------------
// Stage 5: attn + head-mean. z = b; 3 K-segments (one per head) accumulate.
// ---------------------------------------------------------------------------
__global__ void __launch_bounds__(256, 2)
k_attn()
{
    extern __shared__ char dsm[];
    Ids d = make_ids();
    int b = blockIdx.z;
    const __half *Aa[3], *Bb[3];
    #pragma unroll
    for (int h = 0; h < H_; h++) {
        size_t hb = (size_t)(h * B_ + b);
        Aa[h] = g_P + hb * N_ * N_ + (size_t)blockIdx.y * TM * N_;
        Bb[h] = g_V + hb * E_ * N_ + (size_t)blockIdx.x * TN * N_;
    }
    float acc[2][8][4] = {};
    mainloop<3>(Aa[0], Aa[1], Aa[2], Bb[0], Bb[1], Bb[2], N_, N_,
                smem_u32(dsm), d.tid, d.mw, d.nw, d.lane, acc);

    const float sc = 1.0f / (3.0f * 256.0f);    // head-mean + invZ x256 comp
    __half* C = g_mean + (size_t)b * N_ * E_;
    #pragma unroll
    for (int i = 0; i < 2; i++) {
        size_t r = (size_t)blockIdx.y * TM + d.mw + i * 16 + d.qr;
        #pragma unroll
        for (int j = 0; j < 8; j++) {
            int cn = blockIdx.x * TN + d.nw + j * 8 + d.qc * 2;
            *reinterpret_cast<uint32_t*>(&C[r * E_ + cn]) =
                pack_h2(acc[i][j][0] * sc, acc[i][j][1] * sc);
            *reinterpret_cast<uint32_t*>(&C[(r + 8) * E_ + cn]) =
                pack_h2(acc[i][j][2] * sc, acc[i][j][3] * sc);
        }
    }
}

// ---------------------------------------------------------------------------
// Stage 6: out = mean @ fc_w^T + fc_b (bias + output in full fp32).
// ---------------------------------------------------------------------------
__global__ void __launch_bounds__(256, 2)
k_fc(const float* __restrict__ fc_b, float* __restrict__ out)
{
    extern __shared__ char dsm[];
    Ids d = make_ids();
    const __half* A  = g_mean + (size_t)blockIdx.y * TM * E_;
    const __half* Bm = g_fcw + (size_t)blockIdx.x * TN * E_;
    float acc[2][8][4] = {};
    mainloop<1>(A, A, A, Bm, Bm, Bm, E_, E_, smem_u32(dsm),
                d.tid, d.mw, d.nw, d.lane, acc);

    #pragma unroll
    for (int i = 0; i < 2; i++) {
        size_t r = (size_t)blockIdx.y * TM + d.mw + i * 16 + d.qr;
        #pragma unroll
        for (int j = 0; j < 8; j++) {
            int cn = blockIdx.x * TN + d.nw + j * 8 + d.qc * 2;
            float2 bia = *reinterpret_cast<const float2*>(&fc_b[cn]);
            *reinterpret_cast<float2*>(&out[r * E_ + cn]) =
                make_float2(acc[i][j][0] + bia.x, acc[i][j][1] + bia.y);
            *reinterpret_cast<float2*>(&out[(r + 8) * E_ + cn]) =
                make_float2(acc[i][j][2] + bia.x, acc[i][j][3] + bia.y);
        }
    }
}

// ---------------------------------------------------------------------------
extern "C" void kernel_launch(void* const* d_in, const int* in_sizes, int n_in,
                              void* d_out, int out_size)
{
    const float* x    = (const float*)d_in[0];
    const float* Wq   = (const float*)d_in[1];
    const float* Wk   = (const float*)d_in[2];
    const float* Wv   = (const float*)d_in[3];
    const float* fc_w = (const float*)d_in[4];
    const float* fc_b = (const float*)d_in[5];
    float* out = (float*)d_out;

    cudaFuncSetAttribute(k_wgemmM, cudaFuncAttributeMaxDynamicSharedMemorySize, SMEM_GEMM);
    cudaFuncSetAttribute(k_R,      cudaFuncAttributeMaxDynamicSharedMemorySize, SMEM_GEMM);
    cudaFuncSetAttribute(k_projV,  cudaFuncAttributeMaxDynamicSharedMemorySize, SMEM_GEMM);
    cudaFuncSetAttribute(k_scores, cudaFuncAttributeMaxDynamicSharedMemorySize, SMEM_GEMM);
    cudaFuncSetAttribute(k_attn,   cudaFuncAttributeMaxDynamicSharedMemorySize, SMEM_GEMM);
    cudaFuncSetAttribute(k_fc,     cudaFuncAttributeMaxDynamicSharedMemorySize, SMEM_GEMM);

    const size_t nround = (size_t)MT*E_/8 + 3*(size_t)H_*E_*E_/8 + (size_t)E_*E_/8;
    k_round <<<(int)((nround + 255) / 256), 256>>>(x, Wq, Wk, Wv, fc_w);
    k_zeroZ <<<(H_*B_*N_ + 255)/256, 256>>>();
    k_transW<<<dim3(E_/64, E_/64, 2*H_), 256>>>();
    k_wgemmM<<<dim3(E_/TN, E_/TM, H_), 256, SMEM_GEMM>>>();
    k_R     <<<dim3(E_/TN, MT/TM, H_), 256, SMEM_GEMM>>>();
    k_projV <<<dim3(E_/TN, MT/TM, H_), 256, SMEM_GEMM>>>();
    k_scores<<<dim3(N_/TN, N_/TM, H_*B_), 256, SMEM_GEMM>>>();
    k_recipZ<<<(H_*B_*N_ + 255)/256, 256>>>();
    k_scaleV<<<(int)(((size_t)H_*B_*E_*N_/8 + 255)/256), 256>>>();
    k_attn  <<<dim3(E_/TN, N_/TM, B_), 256, SMEM_GEMM>>>();
    k_fc    <<<dim3(E_/TN, MT/TM), 256, SMEM_GEMM>>>(fc_b, out);
}

// round 14
// speedup vs baseline: 10.7537x; 1.0065x over previous
#include <cuda_runtime.h>
#include <cuda_fp16.h>
#include <cstdint>
#include <math.h>

// Problem constants
#define E_ 2048
#define H_ 3
#define B_ 4
#define N_ 2048
#define MT (B_*N_)          // 8192 tokens

// GEMM tile: M=128, N=128, K=64 halfs per chunk; fp16 m16n8k16 HMMA.
// 128 threads (4 warps, 2x2 of 64x64), 3-stage cp.async ring, 1 barrier/chunk,
// 2 CTAs/SM (192KB smem, ~190 regs).
constexpr int TM = 128, TN = 128, TK = 64;
constexpr int NT = 128;                        // threads per CTA
constexpr int STAGES = 3;
constexpr int A_BYTES   = TM * TK * 2;        // 16 KB (128 rows x 128B)
constexpr int B_BYTES   = TN * TK * 2;        // 16 KB
constexpr int BUF_BYTES = A_BYTES + B_BYTES;  // 32 KB
constexpr int SMEM_GEMM = STAGES * BUF_BYTES; // 96 KB
constexpr int CHUNKS_PER_SEG = E_ / TK;       // 32

// Scratch (device globals: allocation-free rule) — fp16 intermediates
__device__ __half g_x  [(size_t)MT*E_];
__device__ __half g_Wq [(size_t)H_*E_*E_];
__device__ __half g_Wk [(size_t)H_*E_*E_];
__device__ __half g_Wv [(size_t)H_*E_*E_];
__device__ __half g_fcw[(size_t)E_*E_];
__device__ __half g_WqT[(size_t)H_*E_*E_];    // [h][e][d] transposed weights
__device__ __half g_WkT[(size_t)H_*E_*E_];
__device__ __half g_M  [(size_t)H_*E_*E_];    // Mt[h][e'][e] = sum_d Wk[d,e']Wq[d,e]
__device__ __half g_R  [(size_t)H_*MT*E_];    // R[h][t][e'] = x @ Mt^T
__device__ __half g_V  [(size_t)H_*B_*N_*E_]; // TRANSPOSED [hb][e][m]
__device__ __half g_P  [(size_t)H_*B_*N_*N_]; // [hb][n][m] = exp(scores)
__device__ float  g_Z  [H_*B_*N_];            // col sums -> 256/Z
__device__ __half g_mean[(size_t)B_*N_*E_];   // [t][e]

// ---------------------------------------------------------------------------
// PTX helpers (plain sm_80+ features only)
// ---------------------------------------------------------------------------
__device__ __forceinline__ uint32_t smem_u32(const void* p) {
    uint32_t a;
    asm("{ .reg .u64 t; cvta.to.shared.u64 t, %1; cvt.u32.u64 %0, t; }"
        : "=r"(a) : "l"(p));
    return a;
}
__device__ __forceinline__ void cp16(uint32_t dst, const void* src) {
    asm volatile("cp.async.cg.shared.global [%0], [%1], 16;" :: "r"(dst), "l"(src));
}
#define CP_COMMIT() asm volatile("cp.async.commit_group;" ::: "memory")
template<int Nw> __device__ __forceinline__ void cp_wait() {
    asm volatile("cp.async.wait_group %0;" :: "n"(Nw) : "memory");
}
__device__ __forceinline__ void ldsm4(uint32_t (&r)[4], uint32_t addr) {
    asm volatile("ldmatrix.sync.aligned.m8n8.x4.shared.b16 {%0,%1,%2,%3}, [%4];"
        : "=r"(r[0]), "=r"(r[1]), "=r"(r[2]), "=r"(r[3]) : "r"(addr));
}
__device__ __forceinline__ void mma_f16(float (&d)[4], const uint32_t (&a)[4],
                                        uint32_t b0, uint32_t b1) {
    asm volatile(
        "mma.sync.aligned.m16n8k16.row.col.f32.f16.f16.f32 "
        "{%0,%1,%2,%3}, {%4,%5,%6,%7}, {%8,%9}, {%0,%1,%2,%3};"
        : "+f"(d[0]), "+f"(d[1]), "+f"(d[2]), "+f"(d[3])
        : "r"(a[0]), "r"(a[1]), "r"(a[2]), "r"(a[3]), "r"(b0), "r"(b1));
}
__device__ __forceinline__ uint32_t pack_h2(float a, float b) {
    __half2 h = __float22half2_rn(make_float2(a, b));
    return *reinterpret_cast<uint32_t*>(&h);
}

// ---------------------------------------------------------------------------
// Prefetch one 128x64 A tile + 128x64 B tile (fp16) via cp.async (128 thr).
// Row = 64 halfs = 128B = 8 x 16B chunks; chunk c swizzled to c ^ (row&7).
// ---------------------------------------------------------------------------
__device__ __forceinline__ void prefetch_tiles(
    const __half* __restrict__ Ag, const __half* __restrict__ Bg,
    int lda, int ldb, int kt, uint32_t sA, uint32_t sB, int tid)
{
    #pragma unroll
    for (int i = 0; i < 8; i++) {
        int f = tid + i * NT, row = f >> 3, c4 = f & 7;
        cp16(sA + row * 128 + ((c4 ^ (row & 7)) << 4),
             Ag + (size_t)row * lda + kt + c4 * 8);
    }
    #pragma unroll
    for (int i = 0; i < 8; i++) {
        int f = tid + i * NT, row = f >> 3, c4 = f & 7;
        cp16(sB + row * 128 + ((c4 ^ (row & 7)) << 4),
             Bg + (size_t)row * ldb + kt + c4 * 8);
    }
}

// ---------------------------------------------------------------------------
// Compute 128x128 += A(128x64) * B(128x64)^T (fp16) from swizzled smem.
// Warp (mw,nw) owns 64x64. 4 k-steps of k=16; 4 A-tiles x 4 B-tiles each.
// ---------------------------------------------------------------------------
__device__ __forceinline__ void compute_tiles(
    uint32_t sA, uint32_t sB, int mw, int nw, int lane, float (&acc)[4][8][4])
{
    const int g  = lane >> 3;
    const int i8 = lane & 7;
    const int rA0 = mw + ((g & 1) << 3) + i8;
    const int rB0 = nw + ((g >> 1) << 3) + i8;
    const int chA = (g >> 1), chB = (g & 1);
    #pragma unroll
    for (int kc = 0; kc < 8; kc += 2) {         // 4 k-steps of 16
        uint32_t a[4][4];
        #pragma unroll
        for (int i = 0; i < 4; i++) {
            int row = rA0 + i * 16, ch = kc + chA;
            ldsm4(a[i], sA + row * 128 + ((ch ^ (row & 7)) << 4));
        }
        #pragma unroll
        for (int j2 = 0; j2 < 4; j2++) {
            uint32_t b[4];
            int row = rB0 + j2 * 16, ch = kc + chB;
            ldsm4(b, sB + row * 128 + ((ch ^ (row & 7)) << 4));
            #pragma unroll
            for (int i = 0; i < 4; i++) {
                mma_f16(acc[i][2*j2],   a[i], b[0], b[1]);
                mma_f16(acc[i][2*j2+1], a[i], b[2], b[3]);
            }
        }
    }
}

// ---------------------------------------------------------------------------
// 3-stage cp.async mainloop with ONE barrier per chunk.
// Prefetch of chunk c+2 targets buffer (c+2)%3 == (c-1)%3; the barrier at
// iteration c proves all threads finished compute(c-1), so the write is safe.
// NSEG K-segments of 2048 (attn uses 3 heads).
// ---------------------------------------------------------------------------
template<int NSEG>
__device__ __forceinline__ void mainloop(
    const __half* A0, const __half* A1, const __half* A2,
    const __half* B0, const __half* B1, const __half* B2,
    int lda, int ldb, uint32_t sbase, int tid, int mw, int nw, int lane,
    float (&acc)[4][8][4])
{
    const int total = NSEG * CHUNKS_PER_SEG;
    prefetch_tiles(A0, B0, lda, ldb, 0, sbase, sbase + A_BYTES, tid);
    CP_COMMIT();
    prefetch_tiles(A0, B0, lda, ldb, TK, sbase + BUF_BYTES,
                   sbase + BUF_BYTES + A_BYTES, tid);
    CP_COMMIT();
    for (int c = 0; c < total; c++) {
        if (c + 1 < total) cp_wait<1>(); else cp_wait<0>();
        __syncthreads();
        int cn = c + 2;
        if (cn < total) {
            int s = cn >> 5;
            const __half* Ag = (s == 0) ? A0 : (s == 1 ? A1 : A2);
            const __half* Bg = (s == 0) ? B0 : (s == 1 ? B1 : B2);
            uint32_t off = (uint32_t)(cn % STAGES) * BUF_BYTES;
            prefetch_tiles(Ag, Bg, lda, ldb, (cn & 31) * TK,
                           sbase + off, sbase + off + A_BYTES, tid);
            CP_COMMIT();
        }
        uint32_t off = (uint32_t)(c % STAGES) * BUF_BYTES;
        compute_tiles(sbase + off, sbase + off + A_BYTES, mw, nw, lane, acc);
    }
}

// Common per-thread ids (4 warps: 2 along M, 2 along N; 64x64 each)
struct Ids { int tid, lane, wid, mw, nw, qr, qc; };
__device__ __forceinline__ Ids make_ids() {
    Ids d;
    d.tid = threadIdx.x; d.lane = d.tid & 31; d.wid = d.tid >> 5;
    d.mw = (d.wid & 1) * 64; d.nw = (d.wid >> 1) * 64;
    d.qr = d.lane >> 2; d.qc = d.lane & 3;
    return d;
}

// Shared fp16 row-major epilogue: write acc (4x8x4) to C[row][col] halves.
__device__ __forceinline__ void store_half_tile(
    __half* C, int ldc, const Ids& d, int by, int bx, float (&acc)[4][8][4])
{
    #pragma unroll
    for (int i = 0; i < 4; i++) {
        size_t r = (size_t)by * TM + d.mw + i * 16 + d.qr;
        #pragma unroll
        for (int j = 0; j < 8; j++) {
            int cn = bx * TN + d.nw + j * 8 + d.qc * 2;
            *reinterpret_cast<uint32_t*>(&C[r * ldc + cn]) =
                pack_h2(acc[i][j][0], acc[i][j][1]);
            *reinterpret_cast<uint32_t*>(&C[(r + 8) * ldc + cn]) =
                pack_h2(acc[i][j][2], acc[i][j][3]);
        }
    }
}

// ---------------------------------------------------------------------------
// Stage 0a: round inputs to fp16 scratch (x, Wq, Wk, Wv, fc_w).
// ---------------------------------------------------------------------------
__global__ void __launch_bounds__(256)
k_round(const float* __restrict__ x,  const float* __restrict__ Wq,
        const float* __restrict__ Wk, const float* __restrict__ Wv,
        const float* __restrict__ fcw)
{
    const size_t nx = (size_t)MT * E_ / 8, nw = (size_t)H_ * E_ * E_ / 8,
                 nf = (size_t)E_ * E_ / 8;
    size_t i = (size_t)blockIdx.x * blockDim.x + threadIdx.x;
    const float* src; __half* dst; size_t off;
    if      (i < nx)            { src = x;   dst = g_x;   off = i; }
    else if (i < nx + nw)       { src = Wq;  dst = g_Wq;  off = i - nx; }
    else if (i < nx + 2*nw)     { src = Wk;  dst = g_Wk;  off = i - nx - nw; }
    else if (i < nx + 3*nw)     { src = Wv;  dst = g_Wv;  off = i - nx - 2*nw; }
    else if (i < nx + 3*nw + nf){ src = fcw; dst = g_fcw; off = i - nx - 3*nw; }
    else return;
    const float4* s4 = reinterpret_cast<const float4*>(src) + off * 2;
    float4 a = s4[0], b = s4[1];
    uint4 u;
    u.x = pack_h2(a.x, a.y); u.y = pack_h2(a.z, a.w);
    u.z = pack_h2(b.x, b.y); u.w = pack_h2(b.z, b.w);
    reinterpret_cast<uint4*>(dst)[off] = u;
}

// ---------------------------------------------------------------------------
// Stage 0b: transpose Wq, Wk (fp16): [h][d][e] -> [h][e][d]. 64x64 tiles.
// ---------------------------------------------------------------------------
__global__ void __launch_bounds__(256)
k_transW()
{
    __shared__ __half s[64][72];     // 144B row stride (16B aligned)
    int z = blockIdx.z;
    const __half* src = (z < H_ ? g_Wq : g_Wk) + (size_t)(z % H_) * E_ * E_;
    __half*       dst = (z < H_ ? g_WqT : g_WkT) + (size_t)(z % H_) * E_ * E_;
    int d0 = blockIdx.y * 64, e0 = blockIdx.x * 64;
    int tid = threadIdx.x;
    #pragma unroll
    for (int i = 0; i < 2; i++) {
        int f = tid + i * 256, r = f >> 3, c8 = (f & 7) * 8;
        uint4 u = *reinterpret_cast<const uint4*>(&src[(size_t)(d0 + r) * E_ + e0 + c8]);
        *reinterpret_cast<uint4*>(&s[r][c8]) = u;
    }
    __syncthreads();
    #pragma unroll
    for (int i = 0; i < 2; i++) {
        int f = tid + i * 256, r = f >> 3, c8 = (f & 7) * 8;
        __half t[8];
        #pragma unroll
        for (int j = 0; j < 8; j++) t[j] = s[c8 + j][r];
        *reinterpret_cast<uint4*>(&dst[(size_t)(e0 + r) * E_ + d0 + c8]) =
            *reinterpret_cast<uint4*>(t);
    }
}

// ---------------------------------------------------------------------------
// Stage 1: Mt_h = WkT_h @ (WqT_h)^T  (E x E per head).
// ---------------------------------------------------------------------------
__global__ void __launch_bounds__(NT, 2)
k_wgemmM()
{
    extern __shared__ char dsm[];
    Ids d = make_ids();
    int h = blockIdx.z;
    const __half* A  = g_WkT + (size_t)h * E_ * E_ + (size_t)blockIdx.y * TM * E_;
    const __half* Bm = g_WqT + (size_t)h * E_ * E_ + (size_t)blockIdx.x * TN * E_;
    float acc[4][8][4] = {};
    mainloop<1>(A, A, A, Bm, Bm, Bm, E_, E_, smem_u32(dsm),
                d.tid, d.mw, d.nw, d.lane, acc);
    store_half_tile(g_M + (size_t)h * E_ * E_, E_, d, blockIdx.y, blockIdx.x, acc);
}

// ---------------------------------------------------------------------------
// Stage 2: R_h = x @ Mt_h^T  ([MT, E] per head).
// ---------------------------------------------------------------------------
__global__ void __launch_bounds__(NT, 2)
k_R()
{
    extern __shared__ char dsm[];
    Ids d = make_ids();
    int h = blockIdx.z;
    const __half* A  = g_x + (size_t)blockIdx.y * TM * E_;
    const __half* Bm = g_M + (size_t)h * E_ * E_ + (size_t)blockIdx.x * TN * E_;
    float acc[4][8][4] = {};
    mainloop<1>(A, A, A, Bm, Bm, Bm, E_, E_, smem_u32(dsm),
                d.tid, d.mw, d.nw, d.lane, acc);
    store_half_tile(g_R + (size_t)h * MT * E_, E_, d, blockIdx.y, blockIdx.x, acc);
}

// ---------------------------------------------------------------------------
// Stage 3: V projection: V = x @ Wv_h^T, stored TRANSPOSED [hb][e][m].
// ---------------------------------------------------------------------------
__global__ void __launch_bounds__(NT, 2)
k_projV()
{
    extern __shared__ char dsm[];
    Ids d = make_ids();
    int h = blockIdx.z;
    const __half* A  = g_x + (size_t)blockIdx.y * TM * E_;
    const __half* Bm = g_Wv + (size_t)h * E_ * E_ + (size_t)blockIdx.x * TN * E_;
    float acc[4][8][4] = {};
    mainloop<1>(A, A, A, Bm, Bm, Bm, E_, E_, smem_u32(dsm),
                d.tid, d.mw, d.nw, d.lane, acc);

    __syncthreads();   // stage buffers now reusable as transpose staging
    // transpose 64x64 warp tile through smem, write coalesced Vt rows
    float* tw = reinterpret_cast<float*>(dsm) + d.wid * (64 * 66);  // [64][66]
    #pragma unroll
    for (int i = 0; i < 4; i++) {
        int ml = i * 16 + d.qr;
        #pragma unroll
        for (int j = 0; j < 8; j++) {
            int el = j * 8 + d.qc * 2;
            tw[(el    ) * 66 + ml    ] = acc[i][j][0];
            tw[(el + 1) * 66 + ml    ] = acc[i][j][1];
            tw[(el    ) * 66 + ml + 8] = acc[i][j][2];
            tw[(el + 1) * 66 + ml + 8] = acc[i][j][3];
        }
    }
    __syncwarp();
    int b  = (blockIdx.y * TM) >> 11;
    int m0 = (blockIdx.y * TM + d.mw) & (N_ - 1);
    size_t basev = (size_t)(h * B_ + b) * E_ * N_;
    #pragma unroll
    for (int it = 0; it < 16; it++) {         // 4 e-rows/iter, 8 halfs/lane
        int el = it * 4 + (d.lane >> 3);
        int m8 = (d.lane & 7) * 8;
        const float* tr = &tw[el * 66 + m8];
        uint4 u;
        u.x = pack_h2(tr[0], tr[1]); u.y = pack_h2(tr[2], tr[3]);
        u.z = pack_h2(tr[4], tr[5]); u.w = pack_h2(tr[6], tr[7]);
        int e = blockIdx.x * TN + d.nw + el;
        *reinterpret_cast<uint4*>(&g_V[basev + (size_t)e * N_ + m0 + m8]) = u;
    }
}

// ---------------------------------------------------------------------------
// Stage 4: scores + exp2 + column sums. P = exp2(s2 * R_hb @ x_b^T).
// Sums accumulate the fp16-ROUNDED values so Z matches what attn-GEMM reads.
// ---------------------------------------------------------------------------
__global__ void __launch_bounds__(NT, 2)
k_scores()
{
    extern __shared__ char dsm[];
    Ids d = make_ids();
    int z = blockIdx.z;                     // z = h*B + b
    const __half* A  = g_R + (size_t)z * N_ * E_ + (size_t)blockIdx.y * TM * E_;
    const __half* Bm = g_x + (size_t)(z % B_) * N_ * E_ + (size_t)blockIdx.x * TN * E_;
    float acc[4][8][4] = {};
    mainloop<1>(A, A, A, Bm, Bm, Bm, E_, E_, smem_u32(dsm),
                d.tid, d.mw, d.nw, d.lane, acc);

    const float s2 = 1.4426950408889634f / sqrtf((float)E_);
    __half* P = g_P + (size_t)z * N_ * N_;
    float* Zb = g_Z + (size_t)z * N_;
    float cs0[8], cs1[8];
    #pragma unroll
    for (int j = 0; j < 8; j++) { cs0[j] = 0.f; cs1[j] = 0.f; }
    #pragma unroll
    for (int i = 0; i < 4; i++) {
        size_t r = (size_t)blockIdx.y * TM + d.mw + i * 16 + d.qr;
        #pragma unroll
        for (int j = 0; j < 8; j++) {
            int cn = blockIdx.x * TN + d.nw + j * 8 + d.qc * 2;
            __half2 h0 = __float22half2_rn(make_float2(
                exp2f(acc[i][j][0] * s2), exp2f(acc[i][j][1] * s2)));
            __half2 h1 = __float22half2_rn(make_float2(
                exp2f(acc[i][j][2] * s2), exp2f(acc[i][j][3] * s2)));
            *reinterpret_cast<__half2*>(&P[r * N_ + cn])       = h0;
            *reinterpret_cast<__half2*>(&P[(r + 8) * N_ + cn]) = h1;
            float2 f0 = __half22float2(h0), f1 = __half22float2(h1);
            cs0[j] += f0.x + f1.x;
            cs1[j] += f0.y + f1.y;
        }
    }
    #pragma unroll
    for (int j = 0; j < 8; j++) {
        float s0 = cs0[j], s1 = cs1[j];
        #pragma unroll
        for (int o = 4; o < 32; o <<= 1) {
            s0 += __shfl_xor_sync(0xFFFFFFFFu, s0, o);
            s1 += __shfl_xor_sync(0xFFFFFFFFu, s1, o);
        }
        if (d.lane < 4) {
            int cn = blockIdx.x * TN + d.nw + j * 8 + d.lane * 2;
            atomicAdd(&Zb[cn], s0);
            atomicAdd(&Zb[cn + 1], s1);
        }
    }
}

// ---------------------------------------------------------------------------
// Helpers: zero Z; Z -> 256/Z (x256 keeps scaled V out of fp16 subnormals;
// compensated by 1/(3*256) in the attn epilogue); Vt *= scaled invZ.
// ---------------------------------------------------------------------------
__global__ void k_zeroZ() {
    int i = blockIdx.x * blockDim.x + threadIdx.x;
    if (i < H_ * B_ * N_) g_Z[i] = 0.0f;
}
__global__ void k_recipZ() {
    int i = blockIdx.x * blockDim.x + threadIdx.x;
    if (i < H_ * B_ * N_) g_Z[i] = 256.0f / g_Z[i];
}
__global__ void __launch_bounds__(256)
k_scaleV() {
    size_t i8 = (size_t)blockIdx.x * blockDim.x + threadIdx.x;   // 8 halfs each
    if (i8 >= (size_t)H_ * B_ * E_ * N_ / 8) return;
    size_t m8 = (i8 % (N_ / 8)) * 8;
    size_t hb = i8 / ((size_t)E_ * N_ / 8);
    uint4 u = reinterpret_cast<uint4*>(g_V)[i8];
    const float* zz = g_Z + hb * N_ + m8;
    float2 v0 = __half22float2(*reinterpret_cast<__half2*>(&u.x));
    float2 v1 = __half22float2(*reinterpret_cast<__half2*>(&u.y));
    float2 v2 = __half22float2(*reinterpret_cast<__half2*>(&u.z));
    float2 v3 = __half22float2(*reinterpret_cast<__half2*>(&u.w));
    u.x = pack_h2(v0.x * zz[0], v0.y * zz[1]);
    u.y = pack_h2(v1.x * zz[2], v1.y * zz[3]);
    u.z = pack_h2(v2.x * zz[4], v2.y * zz[5]);
    u.w = pack_h2(v3.x * zz[6], v3.y * zz[7]);
    reinterpret_cast<uint4*>(g_V)[i8] = u;
}

// ---------------------------------------------------------------------------
// Stage 5: attn + head-mean. z = b; 3 K-segments (one per head) accumulate.
// ---------------------------------------------------------------------------
__global__ void __launch_bounds__(NT, 2)
k_attn()
{
    extern __shared__ char dsm[];
    Ids d = make_ids();
    int b = blockIdx.z;
    const __half *Aa[3], *Bb[3];
    #pragma unroll
    for (int h = 0; h < H_; h++) {
        size_t hb = (size_t)(h * B_ + b);
        Aa[h] = g_P + hb * N_ * N_ + (size_t)blockIdx.y * TM * N_;
        Bb[h] = g_V + hb * E_ * N_ + (size_t)blockIdx.x * TN * N_;
    }
    float acc[4][8][4] = {};
    mainloop<3>(Aa[0], Aa[1], Aa[2], Bb[0], Bb[1], Bb[2], N_, N_,
                smem_u32(dsm), d.tid, d.mw, d.nw, d.lane, acc);

    const float sc = 1.0f / (3.0f * 256.0f);    // head-mean + invZ x256 comp
    __half* C = g_mean + (size_t)b * N_ * E_;
    #pragma unroll
    for (int i = 0; i < 4; i++) {
        size_t r = (size_t)blockIdx.y * TM + d.mw + i * 16 + d.qr;
        #pragma unroll
        for (int j = 0; j < 8; j++) {
            int cn = blockIdx.x * TN + d.nw + j * 8 + d.qc * 2;
            *reinterpret_cast<uint32_t*>(&C[r * E_ + cn]) =
                pack_h2(acc[i][j][0] * sc, acc[i][j][1] * sc);
            *reinterpret_cast<uint32_t*>(&C[(r + 8) * E_ + cn]) =
                pack_h2(acc[i][j][2] * sc, acc[i][j][3] * sc);
        }
    }
}

// ---------------------------------------------------------------------------
// Stage 6: out = mean @ fc_w^T + fc_b (bias + output in full fp32).
// ---------------------------------------------------------------------------
__global__ void __launch_bounds__(NT, 2)
k_fc(const float* __restrict__ fc_b, float* __restrict__ out)
{
    extern __shared__ char dsm[];
    Ids d = make_ids();
    const __half* A  = g_mean + (size_t)blockIdx.y * TM * E_;
    const __half* Bm = g_fcw + (size_t)blockIdx.x * TN * E_;
    float acc[4][8][4] = {};
    mainloop<1>(A, A, A, Bm, Bm, Bm, E_, E_, smem_u32(dsm),
                d.tid, d.mw, d.nw, d.lane, acc);

    #pragma unroll
    for (int i = 0; i < 4; i++) {
        size_t r = (size_t)blockIdx.y * TM + d.mw + i * 16 + d.qr;
        #pragma unroll
        for (int j = 0; j < 8; j++) {
            int cn = blockIdx.x * TN + d.nw + j * 8 + d.qc * 2;
            float2 bia = *reinterpret_cast<const float2*>(&fc_b[cn]);
            *reinterpret_cast<float2*>(&out[r * E_ + cn]) =
                make_float2(acc[i][j][0] + bia.x, acc[i][j][1] + bia.y);
            *reinterpret_cast<float2*>(&out[(r + 8) * E_ + cn]) =
                make_float2(acc[i][j][2] + bia.x, acc[i][j][3] + bia.y);
        }
    }
}

// ---------------------------------------------------------------------------
extern "C" void kernel_launch(void* const* d_in, const int* in_sizes, int n_in,
                              void* d_out, int out_size)
{
    const float* x    = (const float*)d_in[0];
    const float* Wq   = (const float*)d_in[1];
    const float* Wk   = (const float*)d_in[2];
    const float* Wv   = (const float*)d_in[3];
    const float* fc_w = (const float*)d_in[4];
    const float* fc_b = (const float*)d_in[5];
    float* out = (float*)d_out;

    cudaFuncSetAttribute(k_wgemmM, cudaFuncAttributeMaxDynamicSharedMemorySize, SMEM_GEMM);
    cudaFuncSetAttribute(k_R,      cudaFuncAttributeMaxDynamicSharedMemorySize, SMEM_GEMM);
    cudaFuncSetAttribute(k_projV,  cudaFuncAttributeMaxDynamicSharedMemorySize, SMEM_GEMM);
    cudaFuncSetAttribute(k_scores, cudaFuncAttributeMaxDynamicSharedMemorySize, SMEM_GEMM);
    cudaFuncSetAttribute(k_attn,   cudaFuncAttributeMaxDynamicSharedMemorySize, SMEM_GEMM);
    cudaFuncSetAttribute(k_fc,     cudaFuncAttributeMaxDynamicSharedMemorySize, SMEM_GEMM);

    const size_t nround = (size_t)MT*E_/8 + 3*(size_t)H_*E_*E_/8 + (size_t)E_*E_/8;
    k_round <<<(int)((nround + 255) / 256), 256>>>(x, Wq, Wk, Wv, fc_w);
    k_zeroZ <<<(H_*B_*N_ + 255)/256, 256>>>();
    k_transW<<<dim3(E_/64, E_/64, 2*H_), 256>>>();
    k_wgemmM<<<dim3(E_/TN, E_/TM, H_), NT, SMEM_GEMM>>>();
    k_R     <<<dim3(E_/TN, MT/TM, H_), NT, SMEM_GEMM>>>();
    k_projV <<<dim3(E_/TN, MT/TM, H_), NT, SMEM_GEMM>>>();
    k_scores<<<dim3(N_/TN, N_/TM, H_*B_), NT, SMEM_GEMM>>>();
    k_recipZ<<<(H_*B_*N_ + 255)/256, 256>>>();
    k_scaleV<<<(int)(((size_t)H_*B_*E_*N_/8 + 255)/256), 256>>>();
    k_attn  <<<dim3(E_/TN, N_/TM, B_), NT, SMEM_GEMM>>>();
    k_fc    <<<dim3(E_/TN, MT/TM), NT, SMEM_GEMM>>>(fc_b, out);
}

// round 15
// speedup vs baseline: 10.9541x; 1.0186x over previous
#include <cuda_runtime.h>
#include <cuda_fp16.h>
#include <cstdint>
#include <math.h>

// Problem constants
#define E_ 2048
#define H_ 3
#define B_ 4
#define N_ 2048
#define MT (B_*N_)          // 8192 tokens

// GEMM tile: M=128, N=128, K=64 halfs per chunk; fp16 m16n8k16 HMMA.
// 128 threads (4 warps, 2x2 of 64x64), 3-stage cp.async ring, 1 barrier/chunk,
// 2 CTAs/SM.
constexpr int TM = 128, TN = 128, TK = 64;
constexpr int NT = 128;                        // threads per CTA
constexpr int STAGES = 3;
constexpr int A_BYTES   = TM * TK * 2;        // 16 KB (128 rows x 128B)
constexpr int B_BYTES   = TN * TK * 2;        // 16 KB
constexpr int BUF_BYTES = A_BYTES + B_BYTES;  // 32 KB
constexpr int SMEM_GEMM = STAGES * BUF_BYTES; // 96 KB
constexpr int CHUNKS_PER_SEG = E_ / TK;       // 32

// Scratch (device globals: allocation-free rule) — fp16 intermediates
__device__ __half g_x  [(size_t)MT*E_];
__device__ __half g_Wq [(size_t)H_*E_*E_];
__device__ __half g_Wk [(size_t)H_*E_*E_];
__device__ __half g_Wv [(size_t)H_*E_*E_];
__device__ __half g_fcw[(size_t)E_*E_];
__device__ __half g_WqT[(size_t)H_*E_*E_];    // [h][e][d] transposed weights
__device__ __half g_WkT[(size_t)H_*E_*E_];
__device__ __half g_WvT[(size_t)H_*E_*E_];
__device__ __half g_M  [(size_t)H_*E_*E_];    // Mt[h][e'][e] = sum_d Wk[d,e']Wq[d,e]
__device__ __half g_W2 [(size_t)H_*E_*E_];    // W2[h][i][d] = sum_j fcw[i,j]Wv[j,d]
__device__ __half g_R  [(size_t)H_*MT*E_];    // R[h][t][e'] = x @ Mt^T
__device__ __half g_V  [(size_t)H_*B_*N_*E_]; // V2 TRANSPOSED [hb][i][m]
__device__ __half g_P  [(size_t)H_*B_*N_*N_]; // [hb][n][m] = exp(scores)
__device__ float  g_Z  [H_*B_*N_];            // col sums -> 256/Z

// ---------------------------------------------------------------------------
// PTX helpers (plain sm_80+ features only)
// ---------------------------------------------------------------------------
__device__ __forceinline__ uint32_t smem_u32(const void* p) {
    uint32_t a;
    asm("{ .reg .u64 t; cvta.to.shared.u64 t, %1; cvt.u32.u64 %0, t; }"
        : "=r"(a) : "l"(p));
    return a;
}
__device__ __forceinline__ void cp16(uint32_t dst, const void* src) {
    asm volatile("cp.async.cg.shared.global [%0], [%1], 16;" :: "r"(dst), "l"(src));
}
#define CP_COMMIT() asm volatile("cp.async.commit_group;" ::: "memory")
template<int Nw> __device__ __forceinline__ void cp_wait() {
    asm volatile("cp.async.wait_group %0;" :: "n"(Nw) : "memory");
}
__device__ __forceinline__ void ldsm4(uint32_t (&r)[4], uint32_t addr) {
    asm volatile("ldmatrix.sync.aligned.m8n8.x4.shared.b16 {%0,%1,%2,%3}, [%4];"
        : "=r"(r[0]), "=r"(r[1]), "=r"(r[2]), "=r"(r[3]) : "r"(addr));
}
__device__ __forceinline__ void mma_f16(float (&d)[4], const uint32_t (&a)[4],
                                        uint32_t b0, uint32_t b1) {
    asm volatile(
        "mma.sync.aligned.m16n8k16.row.col.f32.f16.f16.f32 "
        "{%0,%1,%2,%3}, {%4,%5,%6,%7}, {%8,%9}, {%0,%1,%2,%3};"
        : "+f"(d[0]), "+f"(d[1]), "+f"(d[2]), "+f"(d[3])
        : "r"(a[0]), "r"(a[1]), "r"(a[2]), "r"(a[3]), "r"(b0), "r"(b1));
}
__device__ __forceinline__ uint32_t pack_h2(float a, float b) {
    __half2 h = __float22half2_rn(make_float2(a, b));
    return *reinterpret_cast<uint32_t*>(&h);
}

// ---------------------------------------------------------------------------
// Prefetch one 128x64 A tile + 128x64 B tile (fp16) via cp.async (128 thr).
// Row = 64 halfs = 128B = 8 x 16B chunks; chunk c swizzled to c ^ (row&7).
// ---------------------------------------------------------------------------
__device__ __forceinline__ void prefetch_tiles(
    const __half* __restrict__ Ag, const __half* __restrict__ Bg,
    int lda, int ldb, int kt, uint32_t sA, uint32_t sB, int tid)
{
    #pragma unroll
    for (int i = 0; i < 8; i++) {
        int f = tid + i * NT, row = f >> 3, c4 = f & 7;
        cp16(sA + row * 128 + ((c4 ^ (row & 7)) << 4),
             Ag + (size_t)row * lda + kt + c4 * 8);
    }
    #pragma unroll
    for (int i = 0; i < 8; i++) {
        int f = tid + i * NT, row = f >> 3, c4 = f & 7;
        cp16(sB + row * 128 + ((c4 ^ (row & 7)) << 4),
             Bg + (size_t)row * ldb + kt + c4 * 8);
    }
}

// ---------------------------------------------------------------------------
// Compute 128x128 += A(128x64) * B(128x64)^T (fp16) from swizzled smem.
// Warp (mw,nw) owns 64x64. 4 k-steps of k=16; 4 A-tiles x 4 B-tiles each.
// ---------------------------------------------------------------------------
__device__ __forceinline__ void compute_tiles(
    uint32_t sA, uint32_t sB, int mw, int nw, int lane, float (&acc)[4][8][4])
{
    const int g  = lane >> 3;
    const int i8 = lane & 7;
    const int rA0 = mw + ((g & 1) << 3) + i8;
    const int rB0 = nw + ((g >> 1) << 3) + i8;
    const int chA = (g >> 1), chB = (g & 1);
    #pragma unroll
    for (int kc = 0; kc < 8; kc += 2) {         // 4 k-steps of 16
        uint32_t a[4][4];
        #pragma unroll
        for (int i = 0; i < 4; i++) {
            int row = rA0 + i * 16, ch = kc + chA;
            ldsm4(a[i], sA + row * 128 + ((ch ^ (row & 7)) << 4));
        }
        #pragma unroll
        for (int j2 = 0; j2 < 4; j2++) {
            uint32_t b[4];
            int row = rB0 + j2 * 16, ch = kc + chB;
            ldsm4(b, sB + row * 128 + ((ch ^ (row & 7)) << 4));
            #pragma unroll
            for (int i = 0; i < 4; i++) {
                mma_f16(acc[i][2*j2],   a[i], b[0], b[1]);
                mma_f16(acc[i][2*j2+1], a[i], b[2], b[3]);
            }
        }
    }
}

// ---------------------------------------------------------------------------
// 3-stage cp.async mainloop with ONE barrier per chunk.
// Prefetch of chunk c+2 targets buffer (c+2)%3 == (c-1)%3; the barrier at
// iteration c proves all threads finished compute(c-1), so the write is safe.
// NSEG K-segments of 2048 (attn uses 3 heads).
// ---------------------------------------------------------------------------
template<int NSEG>
__device__ __forceinline__ void mainloop(
    const __half* A0, const __half* A1, const __half* A2,
    const __half* B0, const __half* B1, const __half* B2,
    int lda, int ldb, uint32_t sbase, int tid, int mw, int nw, int lane,
    float (&acc)[4][8][4])
{
    const int total = NSEG * CHUNKS_PER_SEG;
    prefetch_tiles(A0, B0, lda, ldb, 0, sbase, sbase + A_BYTES, tid);
    CP_COMMIT();
    prefetch_tiles(A0, B0, lda, ldb, TK, sbase + BUF_BYTES,
                   sbase + BUF_BYTES + A_BYTES, tid);
    CP_COMMIT();
    for (int c = 0; c < total; c++) {
        if (c + 1 < total) cp_wait<1>(); else cp_wait<0>();
        __syncthreads();
        int cn = c + 2;
        if (cn < total) {
            int s = cn >> 5;
            const __half* Ag = (s == 0) ? A0 : (s == 1 ? A1 : A2);
            const __half* Bg = (s == 0) ? B0 : (s == 1 ? B1 : B2);
            uint32_t off = (uint32_t)(cn % STAGES) * BUF_BYTES;
            prefetch_tiles(Ag, Bg, lda, ldb, (cn & 31) * TK,
                           sbase + off, sbase + off + A_BYTES, tid);
            CP_COMMIT();
        }
        uint32_t off = (uint32_t)(c % STAGES) * BUF_BYTES;
        compute_tiles(sbase + off, sbase + off + A_BYTES, mw, nw, lane, acc);
    }
}

// Common per-thread ids (4 warps: 2 along M, 2 along N; 64x64 each)
struct Ids { int tid, lane, wid, mw, nw, qr, qc; };
__device__ __forceinline__ Ids make_ids() {
    Ids d;
    d.tid = threadIdx.x; d.lane = d.tid & 31; d.wid = d.tid >> 5;
    d.mw = (d.wid & 1) * 64; d.nw = (d.wid >> 1) * 64;
    d.qr = d.lane >> 2; d.qc = d.lane & 3;
    return d;
}

// Shared fp16 row-major epilogue: write acc (4x8x4) to C[row][col] halves.
__device__ __forceinline__ void store_half_tile(
    __half* C, int ldc, const Ids& d, int by, int bx, float (&acc)[4][8][4])
{
    #pragma unroll
    for (int i = 0; i < 4; i++) {
        size_t r = (size_t)by * TM + d.mw + i * 16 + d.qr;
        #pragma unroll
        for (int j = 0; j < 8; j++) {
            int cn = bx * TN + d.nw + j * 8 + d.qc * 2;
            *reinterpret_cast<uint32_t*>(&C[r * ldc + cn]) =
                pack_h2(acc[i][j][0], acc[i][j][1]);
            *reinterpret_cast<uint32_t*>(&C[(r + 8) * ldc + cn]) =
                pack_h2(acc[i][j][2], acc[i][j][3]);
        }
    }
}

// ---------------------------------------------------------------------------
// Stage 0a: round inputs to fp16 scratch (x, Wq, Wk, Wv, fc_w) + zero g_Z.
// ---------------------------------------------------------------------------
__global__ void __launch_bounds__(256)
k_round(const float* __restrict__ x,  const float* __restrict__ Wq,
        const float* __restrict__ Wk, const float* __restrict__ Wv,
        const float* __restrict__ fcw)
{
    const size_t nx = (size_t)MT * E_ / 8, nw = (size_t)H_ * E_ * E_ / 8,
                 nf = (size_t)E_ * E_ / 8;
    size_t i = (size_t)blockIdx.x * blockDim.x + threadIdx.x;
    if (i < H_ * B_ * N_) g_Z[i] = 0.0f;        // fused zeroZ
    const float* src; __half* dst; size_t off;
    if      (i < nx)            { src = x;   dst = g_x;   off = i; }
    else if (i < nx + nw)       { src = Wq;  dst = g_Wq;  off = i - nx; }
    else if (i < nx + 2*nw)     { src = Wk;  dst = g_Wk;  off = i - nx - nw; }
    else if (i < nx + 3*nw)     { src = Wv;  dst = g_Wv;  off = i - nx - 2*nw; }
    else if (i < nx + 3*nw + nf){ src = fcw; dst = g_fcw; off = i - nx - 3*nw; }
    else return;
    const float4* s4 = reinterpret_cast<const float4*>(src) + off * 2;
    float4 a = s4[0], b = s4[1];
    uint4 u;
    u.x = pack_h2(a.x, a.y); u.y = pack_h2(a.z, a.w);
    u.z = pack_h2(b.x, b.y); u.w = pack_h2(b.z, b.w);
    reinterpret_cast<uint4*>(dst)[off] = u;
}

// ---------------------------------------------------------------------------
// Stage 0b: transpose Wq, Wk, Wv (fp16): [h][d][e] -> [h][e][d]. 64x64 tiles.
// ---------------------------------------------------------------------------
__global__ void __launch_bounds__(256)
k_transW()
{
    __shared__ __half s[64][72];     // 144B row stride (16B aligned)
    int z = blockIdx.z, t = z / H_, h = z % H_;
    const __half* src = (t == 0 ? g_Wq : (t == 1 ? g_Wk : g_Wv)) + (size_t)h * E_ * E_;
    __half*       dst = (t == 0 ? g_WqT : (t == 1 ? g_WkT : g_WvT)) + (size_t)h * E_ * E_;
    int d0 = blockIdx.y * 64, e0 = blockIdx.x * 64;
    int tid = threadIdx.x;
    #pragma unroll
    for (int i = 0; i < 2; i++) {
        int f = tid + i * 256, r = f >> 3, c8 = (f & 7) * 8;
        uint4 u = *reinterpret_cast<const uint4*>(&src[(size_t)(d0 + r) * E_ + e0 + c8]);
        *reinterpret_cast<uint4*>(&s[r][c8]) = u;
    }
    __syncthreads();
    #pragma unroll
    for (int i = 0; i < 2; i++) {
        int f = tid + i * 256, r = f >> 3, c8 = (f & 7) * 8;
        __half t8[8];
        #pragma unroll
        for (int j = 0; j < 8; j++) t8[j] = s[c8 + j][r];
        *reinterpret_cast<uint4*>(&dst[(size_t)(e0 + r) * E_ + d0 + c8]) =
            *reinterpret_cast<uint4*>(t8);
    }
}

// ---------------------------------------------------------------------------
// Stage 1: weight-space GEMMs, z in [0,6):
//   z < 3 : Mt_h = WkT_h @ (WqT_h)^T  -> g_M
//   z >= 3: W2_h = fcw  @ (WvT_h)^T   -> g_W2   (fc folded through V)
// ---------------------------------------------------------------------------
__global__ void __launch_bounds__(NT, 2)
k_wgemmM()
{
    extern __shared__ char dsm[];
    Ids d = make_ids();
    int z = blockIdx.z;
    const __half *A, *Bm; __half* C;
    if (z < H_) {
        A  = g_WkT + (size_t)z * E_ * E_ + (size_t)blockIdx.y * TM * E_;
        Bm = g_WqT + (size_t)z * E_ * E_ + (size_t)blockIdx.x * TN * E_;
        C  = g_M   + (size_t)z * E_ * E_;
    } else {
        int h = z - H_;
        A  = g_fcw + (size_t)blockIdx.y * TM * E_;
        Bm = g_WvT + (size_t)h * E_ * E_ + (size_t)blockIdx.x * TN * E_;
        C  = g_W2  + (size_t)h * E_ * E_;
    }
    float acc[4][8][4] = {};
    mainloop<1>(A, A, A, Bm, Bm, Bm, E_, E_, smem_u32(dsm),
                d.tid, d.mw, d.nw, d.lane, acc);
    store_half_tile(C, E_, d, blockIdx.y, blockIdx.x, acc);
}

// ---------------------------------------------------------------------------
// Stage 2: R_h = x @ Mt_h^T  ([MT, E] per head).
// ---------------------------------------------------------------------------
__global__ void __launch_bounds__(NT, 2)
k_R()
{
    extern __shared__ char dsm[];
    Ids d = make_ids();
    int h = blockIdx.z;
    const __half* A  = g_x + (size_t)blockIdx.y * TM * E_;
    const __half* Bm = g_M + (size_t)h * E_ * E_ + (size_t)blockIdx.x * TN * E_;
    float acc[4][8][4] = {};
    mainloop<1>(A, A, A, Bm, Bm, Bm, E_, E_, smem_u32(dsm),
                d.tid, d.mw, d.nw, d.lane, acc);
    store_half_tile(g_R + (size_t)h * MT * E_, E_, d, blockIdx.y, blockIdx.x, acc);
}

// ---------------------------------------------------------------------------
// Stage 3: V2 projection: V2 = x @ W2_h^T, stored TRANSPOSED [hb][i][m].
// ---------------------------------------------------------------------------
__global__ void __launch_bounds__(NT, 2)
k_projV()
{
    extern __shared__ char dsm[];
    Ids d = make_ids();
    int h = blockIdx.z;
    const __half* A  = g_x + (size_t)blockIdx.y * TM * E_;
    const __half* Bm = g_W2 + (size_t)h * E_ * E_ + (size_t)blockIdx.x * TN * E_;
    float acc[4][8][4] = {};
    mainloop<1>(A, A, A, Bm, Bm, Bm, E_, E_, smem_u32(dsm),
                d.tid, d.mw, d.nw, d.lane, acc);

    __syncthreads();   // stage buffers now reusable as transpose staging
    // transpose 64x64 warp tile through smem, write coalesced Vt rows
    float* tw = reinterpret_cast<float*>(dsm) + d.wid * (64 * 66);  // [64][66]
    #pragma unroll
    for (int i = 0; i < 4; i++) {
        int ml = i * 16 + d.qr;
        #pragma unroll
        for (int j = 0; j < 8; j++) {
            int el = j * 8 + d.qc * 2;
            tw[(el    ) * 66 + ml    ] = acc[i][j][0];
            tw[(el + 1) * 66 + ml    ] = acc[i][j][1];
            tw[(el    ) * 66 + ml + 8] = acc[i][j][2];
            tw[(el + 1) * 66 + ml + 8] = acc[i][j][3];
        }
    }
    __syncwarp();
    int b  = (blockIdx.y * TM) >> 11;
    int m0 = (blockIdx.y * TM + d.mw) & (N_ - 1);
    size_t basev = (size_t)(h * B_ + b) * E_ * N_;
    #pragma unroll
    for (int it = 0; it < 16; it++) {         // 4 e-rows/iter, 8 halfs/lane
        int el = it * 4 + (d.lane >> 3);
        int m8 = (d.lane & 7) * 8;
        const float* tr = &tw[el * 66 + m8];
        uint4 u;
        u.x = pack_h2(tr[0], tr[1]); u.y = pack_h2(tr[2], tr[3]);
        u.z = pack_h2(tr[4], tr[5]); u.w = pack_h2(tr[6], tr[7]);
        int e = blockIdx.x * TN + d.nw + el;
        *reinterpret_cast<uint4*>(&g_V[basev + (size_t)e * N_ + m0 + m8]) = u;
    }
}

// ---------------------------------------------------------------------------
// Stage 4: scores + exp2 + column sums. P = exp2(s2 * R_hb @ x_b^T).
// Sums accumulate the fp16-ROUNDED values so Z matches what attn-GEMM reads.
// ---------------------------------------------------------------------------
__global__ void __launch_bounds__(NT, 2)
k_scores()
{
    extern __shared__ char dsm[];
    Ids d = make_ids();
    int z = blockIdx.z;                     // z = h*B + b
    const __half* A  = g_R + (size_t)z * N_ * E_ + (size_t)blockIdx.y * TM * E_;
    const __half* Bm = g_x + (size_t)(z % B_) * N_ * E_ + (size_t)blockIdx.x * TN * E_;
    float acc[4][8][4] = {};
    mainloop<1>(A, A, A, Bm, Bm, Bm, E_, E_, smem_u32(dsm),
                d.tid, d.mw, d.nw, d.lane, acc);

    const float s2 = 1.4426950408889634f / sqrtf((float)E_);
    __half* P = g_P + (size_t)z * N_ * N_;
    float* Zb = g_Z + (size_t)z * N_;
    float cs0[8], cs1[8];
    #pragma unroll
    for (int j = 0; j < 8; j++) { cs0[j] = 0.f; cs1[j] = 0.f; }
    #pragma unroll
    for (int i = 0; i < 4; i++) {
        size_t r = (size_t)blockIdx.y * TM + d.mw + i * 16 + d.qr;
        #pragma unroll
        for (int j = 0; j < 8; j++) {
            int cn = blockIdx.x * TN + d.nw + j * 8 + d.qc * 2;
            __half2 h0 = __float22half2_rn(make_float2(
                exp2f(acc[i][j][0] * s2), exp2f(acc[i][j][1] * s2)));
            __half2 h1 = __float22half2_rn(make_float2(
                exp2f(acc[i][j][2] * s2), exp2f(acc[i][j][3] * s2)));
            *reinterpret_cast<__half2*>(&P[r * N_ + cn])       = h0;
            *reinterpret_cast<__half2*>(&P[(r + 8) * N_ + cn]) = h1;
            float2 f0 = __half22float2(h0), f1 = __half22float2(h1);
            cs0[j] += f0.x + f1.x;
            cs1[j] += f0.y + f1.y;
        }
    }
    #pragma unroll
    for (int j = 0; j < 8; j++) {
        float s0 = cs0[j], s1 = cs1[j];
        #pragma unroll
        for (int o = 4; o < 32; o <<= 1) {
            s0 += __shfl_xor_sync(0xFFFFFFFFu, s0, o);
            s1 += __shfl_xor_sync(0xFFFFFFFFu, s1, o);
        }
        if (d.lane < 4) {
            int cn = blockIdx.x * TN + d.nw + j * 8 + d.lane * 2;
            atomicAdd(&Zb[cn], s0);
            atomicAdd(&Zb[cn + 1], s1);
        }
    }
}

// ---------------------------------------------------------------------------
// Helpers: Z -> 256/Z (x256 keeps scaled V out of fp16 subnormals;
// compensated by 1/(3*256) in the attn epilogue); Vt *= scaled invZ.
// ---------------------------------------------------------------------------
__global__ void k_recipZ() {
    int i = blockIdx.x * blockDim.x + threadIdx.x;
    if (i < H_ * B_ * N_) g_Z[i] = 256.0f / g_Z[i];
}
__global__ void __launch_bounds__(256)
k_scaleV() {
    size_t i8 = (size_t)blockIdx.x * blockDim.x + threadIdx.x;   // 8 halfs each
    if (i8 >= (size_t)H_ * B_ * E_ * N_ / 8) return;
    size_t m8 = (i8 % (N_ / 8)) * 8;
    size_t hb = i8 / ((size_t)E_ * N_ / 8);
    uint4 u = reinterpret_cast<uint4*>(g_V)[i8];
    const float* zz = g_Z + hb * N_ + m8;
    float2 v0 = __half22float2(*reinterpret_cast<__half2*>(&u.x));
    float2 v1 = __half22float2(*reinterpret_cast<__half2*>(&u.y));
    float2 v2 = __half22float2(*reinterpret_cast<__half2*>(&u.z));
    float2 v3 = __half22float2(*reinterpret_cast<__half2*>(&u.w));
    u.x = pack_h2(v0.x * zz[0], v0.y * zz[1]);
    u.y = pack_h2(v1.x * zz[2], v1.y * zz[3]);
    u.z = pack_h2(v2.x * zz[4], v2.y * zz[5]);
    u.w = pack_h2(v3.x * zz[6], v3.y * zz[7]);
    reinterpret_cast<uint4*>(g_V)[i8] = u;
}

// ---------------------------------------------------------------------------
// Stage 5: attn + head-mean + fc (folded) -> fp32 out with bias.
// z = b; 3 K-segments (one per head) accumulate in fp32.
// out[b*N + n][i] = (1/(3*256)) * sum_h P_h @ V2s_h + fc_b[i]
// ---------------------------------------------------------------------------
__global__ void __launch_bounds__(NT, 2)
k_attn(const float* __restrict__ fc_b, float* __restrict__ out)
{
    extern __shared__ char dsm[];
    Ids d = make_ids();
    int b = blockIdx.z;
    const __half *Aa[3], *Bb[3];
    #pragma unroll
    for (int h = 0; h < H_; h++) {
        size_t hb = (size_t)(h * B_ + b);
        Aa[h] = g_P + hb * N_ * N_ + (size_t)blockIdx.y * TM * N_;
        Bb[h] = g_V + hb * E_ * N_ + (size_t)blockIdx.x * TN * N_;
    }
    float acc[4][8][4] = {};
    mainloop<3>(Aa[0], Aa[1], Aa[2], Bb[0], Bb[1], Bb[2], N_, N_,
                smem_u32(dsm), d.tid, d.mw, d.nw, d.lane, acc);

    const float sc = 1.0f / (3.0f * 256.0f);    // head-mean + invZ x256 comp
    float* C = out + (size_t)b * N_ * E_;
    #pragma unroll
    for (int i = 0; i < 4; i++) {
        size_t r = (size_t)blockIdx.y * TM + d.mw + i * 16 + d.qr;
        #pragma unroll
        for (int j = 0; j < 8; j++) {
            int cn = blockIdx.x * TN + d.nw + j * 8 + d.qc * 2;
            float2 bia = *reinterpret_cast<const float2*>(&fc_b[cn]);
            *reinterpret_cast<float2*>(&C[r * E_ + cn]) =
                make_float2(acc[i][j][0] * sc + bia.x, acc[i][j][1] * sc + bia.y);
            *reinterpret_cast<float2*>(&C[(r + 8) * E_ + cn]) =
                make_float2(acc[i][j][2] * sc + bia.x, acc[i][j][3] * sc + bia.y);
        }
    }
}

// ---------------------------------------------------------------------------
extern "C" void kernel_launch(void* const* d_in, const int* in_sizes, int n_in,
                              void* d_out, int out_size)
{
    const float* x    = (const float*)d_in[0];
    const float* Wq   = (const float*)d_in[1];
    const float* Wk   = (const float*)d_in[2];
    const float* Wv   = (const float*)d_in[3];
    const float* fc_w = (const float*)d_in[4];
    const float* fc_b = (const float*)d_in[5];
    float* out = (float*)d_out;

    cudaFuncSetAttribute(k_wgemmM, cudaFuncAttributeMaxDynamicSharedMemorySize, SMEM_GEMM);
    cudaFuncSetAttribute(k_R,      cudaFuncAttributeMaxDynamicSharedMemorySize, SMEM_GEMM);
    cudaFuncSetAttribute(k_projV,  cudaFuncAttributeMaxDynamicSharedMemorySize, SMEM_GEMM);
    cudaFuncSetAttribute(k_scores, cudaFuncAttributeMaxDynamicSharedMemorySize, SMEM_GEMM);
    cudaFuncSetAttribute(k_attn,   cudaFuncAttributeMaxDynamicSharedMemorySize, SMEM_GEMM);

    const size_t nround = (size_t)MT*E_/8 + 3*(size_t)H_*E_*E_/8 + (size_t)E_*E_/8;
    k_round <<<(int)((nround + 255) / 256), 256>>>(x, Wq, Wk, Wv, fc_w);
    k_transW<<<dim3(E_/64, E_/64, 3*H_), 256>>>();
    k_wgemmM<<<dim3(E_/TN, E_/TM, 2*H_), NT, SMEM_GEMM>>>();
    k_R     <<<dim3(E_/TN, MT/TM, H_), NT, SMEM_GEMM>>>();
    k_projV <<<dim3(E_/TN, MT/TM, H_), NT, SMEM_GEMM>>>();
    k_scores<<<dim3(N_/TN, N_/TM, H_*B_), NT, SMEM_GEMM>>>();
    k_recipZ<<<(H_*B_*N_ + 255)/256, 256>>>();
    k_scaleV<<<(int)(((size_t)H_*B_*E_*N_/8 + 255)/256), 256>>>();
    k_attn  <<<dim3(E_/TN, N_/TM, B_), NT, SMEM_GEMM>>>(fc_b, out);
}